// round 13
// baseline (speedup 1.0000x reference)
#include <cuda_runtime.h>
#include <cuda_fp16.h>
#include <math.h>

// ---------------- constants ----------------
#define T        2048
#define HIDDEN   2048
#define NHEADS   32
#define NKV      8
#define HDIM     128
#define QSIZE    (NHEADS * HDIM)          // 4096
#define KVSIZE   (NKV * HDIM)             // 1024
#define QKVW     (QSIZE + 2 * KVSIZE)     // 6144
#define SCALING  0.08838834764831845f     // 1/sqrt(128)
#define LOG2E    1.4426950408889634f
#define L2_10000_D64 0.20762050593046f    // log2(10000)/64

#define NQB      (T / 128)                // 16 q-tiles per head
#define NTILES   (NQB * NHEADS)           // 512
#define FGRID    296                      // 2 CTAs x 148 SMs

// ---------------- scratch (no allocations allowed) ----------------
__device__ __half g_qkv16[T * QKVW];           // fp16 qkv (gemm out)
__device__ __half g_h16[T * HIDDEN];           // hidden fp16
__device__ __half g_wqkv16[QKVW * HIDDEN];     // wqkv fp16
__device__ __half g_wo16[HIDDEN * QSIZE];      // wo fp16
__device__ __half g_q16[NHEADS * T * HDIM];    // head-major, scaled by 1/sqrt(D)*log2e
__device__ __half g_k16[NKV * T * HDIM];       // head-major
__device__ __half g_o16[T * QSIZE];            // attention out fp16

// ---------------- ptx helpers ----------------
__device__ __forceinline__ unsigned smem_u32(const void* p) {
    return (unsigned)__cvta_generic_to_shared(p);
}
__device__ __forceinline__ void ldsm4(unsigned r[4], unsigned addr) {
    asm volatile("ldmatrix.sync.aligned.m8n8.x4.shared.b16 {%0,%1,%2,%3},[%4];"
                 : "=r"(r[0]), "=r"(r[1]), "=r"(r[2]), "=r"(r[3]) : "r"(addr));
}
__device__ __forceinline__ void ldsm4t(unsigned r[4], unsigned addr) {
    asm volatile("ldmatrix.sync.aligned.m8n8.x4.trans.shared.b16 {%0,%1,%2,%3},[%4];"
                 : "=r"(r[0]), "=r"(r[1]), "=r"(r[2]), "=r"(r[3]) : "r"(addr));
}
__device__ __forceinline__ void mma_f16(float c[4], const unsigned a[4],
                                        unsigned b0, unsigned b1) {
    asm volatile("mma.sync.aligned.m16n8k16.row.col.f32.f16.f16.f32 "
                 "{%0,%1,%2,%3},{%4,%5,%6,%7},{%8,%9},{%0,%1,%2,%3};"
                 : "+f"(c[0]), "+f"(c[1]), "+f"(c[2]), "+f"(c[3])
                 : "r"(a[0]), "r"(a[1]), "r"(a[2]), "r"(a[3]), "r"(b0), "r"(b1));
}
__device__ __forceinline__ void cp16(unsigned saddr, const void* g) {
    asm volatile("cp.async.cg.shared.global [%0],[%1],16;" :: "r"(saddr), "l"(g));
}
__device__ __forceinline__ void cp_commit() {
    asm volatile("cp.async.commit_group;");
}
template <int N>
__device__ __forceinline__ void cp_wait() {
    asm volatile("cp.async.wait_group %0;" :: "n"(N));
}
__device__ __forceinline__ unsigned pack_h2(float a, float b) {
    __half2 h = __floats2half2_rn(a, b);
    return *reinterpret_cast<unsigned*>(&h);
}
// two exps in one MUFU op; result is the packed fp16 pair for the PV MMA
__device__ __forceinline__ unsigned h2exp2(unsigned x) {
    unsigned r;
    asm("ex2.approx.f16x2 %0, %1;" : "=r"(r) : "r"(x));
    return r;
}

// =====================================================================
// fp32 -> fp16 convert (grid-stride, float4 granularity)
// =====================================================================
__global__ void f2h_kernel(const float* __restrict__ src,
                           __half* __restrict__ dst, long n)
{
    long i = ((long)blockIdx.x * blockDim.x + threadIdx.x) * 4;
    long stride = (long)gridDim.x * blockDim.x * 4;
    for (; i < n; i += stride) {
        float4 v = *(const float4*)(src + i);
        *(__half2*)(dst + i)     = __floats2half2_rn(v.x, v.y);
        *(__half2*)(dst + i + 2) = __floats2half2_rn(v.z, v.w);
    }
}

// =====================================================================
// fp16 tensor-core GEMM: C[M,N] = A[M,K](h) * B[N,K](h)^T, OutT out.
// 128x128 block, BK=64, 2-stage cp.async double buffer, 256 threads,
// 3 CTAs/SM (221 KB smem/SM): cross-CTA latency hiding.
// =====================================================================
#define GSTRH 72
#define STAGE_H (256 * GSTRH)             // halves per stage (A128 + B128 rows)
#define GS 2
#define GEMM_SMEM (GS * STAGE_H * 2)      // 73728 B

template <typename OutT>
__global__ __launch_bounds__(256, 3) void gemm_h16(
    const __half* __restrict__ A, const __half* __restrict__ B,
    OutT* __restrict__ C, int M, int N, int K)
{
    extern __shared__ __half smh[];

    int tid = threadIdx.x;
    int lane = tid & 31, warp = tid >> 5;
    int gid = lane >> 2, tig = lane & 3;
    int wm = warp >> 2, wn = warp & 3;
    int m0 = blockIdx.y * 128, n0 = blockIdx.x * 128;

    int ch   = tid & 7;        // 16B chunk (8 halves)
    int row0 = tid >> 3;       // 0..31
    const __half* gsrc[8];
#pragma unroll
    for (int i = 0; i < 8; i++) {
        int row = row0 + 32 * i;
        gsrc[i] = (row < 128 ? A + (long)(m0 + row) * K
                             : B + (long)(n0 + row - 128) * K) + ch * 8;
    }
    unsigned sdst[8];
#pragma unroll
    for (int i = 0; i < 8; i++)
        sdst[i] = smem_u32(smh + (row0 + 32 * i) * GSTRH + ch * 8);

    float acc[4][4][4];
#pragma unroll
    for (int mt = 0; mt < 4; mt++)
#pragma unroll
        for (int nt = 0; nt < 4; nt++)
#pragma unroll
            for (int r = 0; r < 4; r++) acc[mt][nt][r] = 0.f;

    int nk = K >> 6;   // 64-wide k tiles

    // prologue: stage 0
#pragma unroll
    for (int i = 0; i < 8; i++)
        cp16(sdst[i], gsrc[i]);
    cp_commit();

    for (int k = 0; k < nk; k++) {
        cp_wait<0>();
        __syncthreads();   // stage k%2 ready; prev iter's compute done

        // issue loads for stage (k+1)%2 (stage computed at iter k-1)
        if (k + 1 < nk) {
            int sb = ((k + 1) & 1) * (STAGE_H * 2);
            long kof = (long)(k + 1) * 64;
#pragma unroll
            for (int i = 0; i < 8; i++)
                cp16(sdst[i] + sb, gsrc[i] + kof);
        }
        cp_commit();

        // compute stage k%2
        const __half* Ac = smh + (k & 1) * STAGE_H;
        const __half* Bc = Ac + 128 * GSTRH;
#pragma unroll
        for (int kc = 0; kc < 4; kc++) {
            unsigned aq[4][4], bk[2][4];
#pragma unroll
            for (int mt = 0; mt < 4; mt++) {
                int row = wm * 64 + mt * 16 + (lane & 15);
                int c2  = kc * 2 + (lane >> 4);
                ldsm4(aq[mt], smem_u32(Ac + row * GSTRH + c2 * 8));
            }
#pragma unroll
            for (int ntp = 0; ntp < 2; ntp++) {
                int row = wn * 32 + ntp * 16 + (lane & 7) + ((lane >> 4) << 3);
                int c2  = kc * 2 + ((lane >> 3) & 1);
                ldsm4(bk[ntp], smem_u32(Bc + row * GSTRH + c2 * 8));
            }
#pragma unroll
            for (int mt = 0; mt < 4; mt++)
#pragma unroll
                for (int ntp = 0; ntp < 2; ntp++) {
                    mma_f16(acc[mt][2*ntp],   aq[mt], bk[ntp][0], bk[ntp][1]);
                    mma_f16(acc[mt][2*ntp+1], aq[mt], bk[ntp][2], bk[ntp][3]);
                }
        }
        // single barrier per iter (top of loop)
    }

    // epilogue
#pragma unroll
    for (int mt = 0; mt < 4; mt++) {
        int row = m0 + wm * 64 + mt * 16 + gid;
#pragma unroll
        for (int nt = 0; nt < 4; nt++) {
            int col = n0 + wn * 32 + nt * 8 + 2 * tig;
            if (sizeof(OutT) == 4) {
                *(float2*)&((float*)C)[(long)row * N + col] =
                    make_float2(acc[mt][nt][0], acc[mt][nt][1]);
                *(float2*)&((float*)C)[(long)(row + 8) * N + col] =
                    make_float2(acc[mt][nt][2], acc[mt][nt][3]);
            } else {
                *(__half2*)&((__half*)C)[(long)row * N + col] =
                    __floats2half2_rn(acc[mt][nt][0], acc[mt][nt][1]);
                *(__half2*)&((__half*)C)[(long)(row + 8) * N + col] =
                    __floats2half2_rn(acc[mt][nt][2], acc[mt][nt][3]);
            }
        }
    }
}

// =====================================================================
// Fused per-head RMSNorm + RoPE. One block per t, 512 threads =
// 4 head-slots x 128. sincos table computed ONCE per t into smem.
// =====================================================================
__global__ __launch_bounds__(512) void rmsnorm_rope_kernel(
    const __half* __restrict__ qkv, const int* __restrict__ positions,
    const float* __restrict__ qw, const float* __restrict__ kw,
    __half* __restrict__ q16, __half* __restrict__ k16)
{
    int t   = blockIdx.x;
    int tid = threadIdx.x;
    int g   = tid >> 7;            // head slot 0..3
    int d   = tid & 127;           // 0..127
    int lane = d & 31, wp = d >> 5;

    __shared__ float scos[64], ssin[64];
    __shared__ float sred[4][4];
    __shared__ float snorm[4];
    __shared__ float sx[4][HDIM];

    if (tid < 64) {
        float pos  = (float)positions[t];
        float invf = exp2f(-(float)tid * L2_10000_D64);
        float ang  = pos * invf;
        float c, s;
        sincosf(ang, &s, &c);
        scos[tid] = c;
        ssin[tid] = s;
    }
    __syncthreads();

#pragma unroll
    for (int iter = 0; iter < 10; iter++) {
        int hh = iter * 4 + g;     // 0..39
        bool isq = (hh < NHEADS);
        int off = isq ? hh * HDIM : QSIZE + (hh - NHEADS) * HDIM;
        const float* w = isq ? qw : kw;
        const __half* x = qkv + (long)t * QKVW + off;
        __half* outp = isq ? (q16 + ((long)hh * T + t) * HDIM)
                           : (k16 + ((long)(hh - NHEADS) * T + t) * HDIM);
        float oscale = isq ? SCALING * LOG2E : 1.0f;

        float v = __half2float(x[d]);
        float ss = v * v;
#pragma unroll
        for (int o = 16; o >= 1; o >>= 1)
            ss += __shfl_xor_sync(0xffffffffu, ss, o);
        if (lane == 0) sred[g][wp] = ss;
        __syncthreads();
        if (d == 0) {
            float tot = sred[g][0] + sred[g][1] + sred[g][2] + sred[g][3];
            snorm[g] = rsqrtf(tot / (float)HDIM + 1e-6f);
        }
        __syncthreads();

        float nv = v * snorm[g] * w[d];
        sx[g][d] = nv;
        __syncthreads();

        if (d < 64) {
            float x1 = sx[g][d];
            float x2 = sx[g][d + 64];
            float c = scos[d], s = ssin[d];
            outp[d]      = __float2half_rn((x1 * c - x2 * s) * oscale);
            outp[d + 64] = __float2half_rn((x2 * c + x1 * s) * oscale);
        }
        __syncthreads();   // protect sx/sred for next iter
    }
}

// =====================================================================
// fp16 flash attention (causal, GQA). Output fp16.
// Balanced 296-CTA schedule (2/SM), antipodal two-tile pairing,
// diagonal warp-skip, ex2.approx.f16x2 softmax, predicated rescale.
// =====================================================================
#define FSTR 136
#define FQ_H (128 * FSTR)
#define FKV_H (64 * FSTR)
#define FLASH_SMEM ((FQ_H + 4 * FKV_H) * 2)   // 104448 B

__global__ __launch_bounds__(256, 2) void flash_h16(
    const __half* __restrict__ Q, const __half* __restrict__ Kh,
    const __half* __restrict__ qkv16, __half* __restrict__ O)
{
    extern __shared__ __half smf[];
    __half* Qs = smf;                 // [128][136]
    __half* Ks = smf + FQ_H;          // [2][64][136]
    __half* Vs = Ks + 2 * FKV_H;      // [2][64][136]

    int cta = blockIdx.x;             // 0..295
    int tid = threadIdx.x;
    int lane = tid & 31, warp = tid >> 5;
    int gid = lane >> 2, tig = lane & 3;

    for (int ti = 0; ti < 2; ti++) {
        int t;
        if (ti == 0) {
            t = cta;                          // tiles 0..295 (big half)
        } else {
            if (cta < 80) break;              // no second tile
            t = (NTILES - 1) - (cta - 80);    // cta=80 -> 511, cta=295 -> 296
        }
        int qb = (NQB - 1) - (t >> 5);        // descending work order
        int h  = t & 31;
        int kvh = h >> 2;
        int q0 = qb * 128;

        const __half* Qg = Q + ((long)h * T + q0) * HDIM;
        const __half* Kg = Kh + (long)kvh * T * HDIM;
        const __half* Vg = qkv16 + QSIZE + KVSIZE + kvh * HDIM;   // + t*QKVW

        __syncthreads();   // smem from previous tile fully consumed

        // prologue: Q tile + KV block 0
#pragma unroll
        for (int i = 0; i < 8; i++) {
            int idx = tid + i * 256;
            int r = idx >> 4, c = idx & 15;
            cp16(smem_u32(Qs + r * FSTR + c * 8), Qg + r * HDIM + c * 8);
        }
#pragma unroll
        for (int i = 0; i < 4; i++) {
            int idx = tid + i * 256;
            int r = idx >> 4, c = idx & 15;
            cp16(smem_u32(Ks + r * FSTR + c * 8), Kg + (long)r * HDIM + c * 8);
            cp16(smem_u32(Vs + r * FSTR + c * 8), Vg + (long)r * QKVW + c * 8);
        }
        cp_commit();

        float m0s = -1e30f, m1s = -1e30f, l0s = 0.f, l1s = 0.f;
        float oacc[16][4];
#pragma unroll
        for (int nt = 0; nt < 16; nt++)
#pragma unroll
            for (int r = 0; r < 4; r++) oacc[nt][r] = 0.f;

        int r0 = q0 + warp * 16 + gid;
        int r1 = r0 + 8;
        int kbmax = 2 * qb + 1;

        for (int kb = 0; kb <= kbmax; kb++) {
            cp_wait<0>();
            __syncthreads();

            if (kb < kbmax) {
                __half* Kn = Ks + ((kb + 1) & 1) * FKV_H;
                __half* Vn = Vs + ((kb + 1) & 1) * FKV_H;
                long rowoff = (long)(kb + 1) * 64;
#pragma unroll
                for (int i = 0; i < 4; i++) {
                    int idx = tid + i * 256;
                    int r = idx >> 4, c = idx & 15;
                    cp16(smem_u32(Kn + r * FSTR + c * 8), Kg + (rowoff + r) * HDIM + c * 8);
                    cp16(smem_u32(Vn + r * FSTR + c * 8), Vg + (rowoff + r) * QKVW + c * 8);
                }
            }
            cp_commit();

            // diagonal half-block: warps 0-3 fully masked -> exact skip
            if (kb == kbmax && warp < 4) continue;

            const __half* Kc = Ks + (kb & 1) * FKV_H;
            const __half* Vc = Vs + (kb & 1) * FKV_H;

            // ---- S = Q K^T ----
            float sacc[8][4];
#pragma unroll
            for (int nt = 0; nt < 8; nt++)
#pragma unroll
                for (int r = 0; r < 4; r++) sacc[nt][r] = 0.f;

#pragma unroll
            for (int kc = 0; kc < 8; kc++) {
                unsigned aq[4];
                {
                    int row = warp * 16 + (lane & 15);
                    int c2  = kc * 2 + (lane >> 4);
                    ldsm4(aq, smem_u32(Qs + row * FSTR + c2 * 8));
                }
#pragma unroll
                for (int ntp = 0; ntp < 4; ntp++) {
                    unsigned bk[4];
                    int row = ntp * 16 + (lane & 7) + ((lane >> 4) << 3);
                    int c2  = kc * 2 + ((lane >> 3) & 1);
                    ldsm4(bk, smem_u32(Kc + row * FSTR + c2 * 8));
                    mma_f16(sacc[2*ntp],   aq, bk[0], bk[1]);
                    mma_f16(sacc[2*ntp+1], aq, bk[2], bk[3]);
                }
            }

            // ---- causal mask (last two kv blocks only) ----
            if (kb >= 2 * qb) {
#pragma unroll
                for (int nt = 0; nt < 8; nt++) {
                    int colb = kb * 64 + nt * 8 + 2 * tig;
                    if (colb > r0)     sacc[nt][0] = -1e30f;
                    if (colb + 1 > r0) sacc[nt][1] = -1e30f;
                    if (colb > r1)     sacc[nt][2] = -1e30f;
                    if (colb + 1 > r1) sacc[nt][3] = -1e30f;
                }
            }

            // ---- online softmax (fp16x2 exps, predicated rescale) ----
            float mx0 = -1e30f, mx1 = -1e30f;
#pragma unroll
            for (int nt = 0; nt < 8; nt++) {
                mx0 = fmaxf(mx0, fmaxf(sacc[nt][0], sacc[nt][1]));
                mx1 = fmaxf(mx1, fmaxf(sacc[nt][2], sacc[nt][3]));
            }
            mx0 = fmaxf(mx0, __shfl_xor_sync(0xffffffffu, mx0, 1));
            mx0 = fmaxf(mx0, __shfl_xor_sync(0xffffffffu, mx0, 2));
            mx1 = fmaxf(mx1, __shfl_xor_sync(0xffffffffu, mx1, 1));
            mx1 = fmaxf(mx1, __shfl_xor_sync(0xffffffffu, mx1, 2));

            float mn0 = fmaxf(m0s, mx0);
            float mn1 = fmaxf(m1s, mx1);
            bool rescale = (mn0 > m0s) || (mn1 > m1s);

            unsigned pexp[8][2];
            float ls0 = 0.f, ls1 = 0.f;
#pragma unroll
            for (int nt = 0; nt < 8; nt++) {
                unsigned e01 = h2exp2(pack_h2(sacc[nt][0] - mn0, sacc[nt][1] - mn0));
                unsigned e23 = h2exp2(pack_h2(sacc[nt][2] - mn1, sacc[nt][3] - mn1));
                pexp[nt][0] = e01;
                pexp[nt][1] = e23;
                float2 f01 = __half22float2(*reinterpret_cast<__half2*>(&e01));
                float2 f23 = __half22float2(*reinterpret_cast<__half2*>(&e23));
                ls0 += f01.x + f01.y;
                ls1 += f23.x + f23.y;
            }
            ls0 += __shfl_xor_sync(0xffffffffu, ls0, 1);
            ls0 += __shfl_xor_sync(0xffffffffu, ls0, 2);
            ls1 += __shfl_xor_sync(0xffffffffu, ls1, 1);
            ls1 += __shfl_xor_sync(0xffffffffu, ls1, 2);

            if (rescale) {
                float corr0 = exp2f(m0s - mn0);
                float corr1 = exp2f(m1s - mn1);
                l0s = l0s * corr0 + ls0;
                l1s = l1s * corr1 + ls1;
#pragma unroll
                for (int nt = 0; nt < 16; nt++) {
                    oacc[nt][0] *= corr0;
                    oacc[nt][1] *= corr0;
                    oacc[nt][2] *= corr1;
                    oacc[nt][3] *= corr1;
                }
                m0s = mn0;
                m1s = mn1;
            } else {
                l0s += ls0;
                l1s += ls1;
            }

            // ---- O += P V (P fragments come straight from h2exp2) ----
#pragma unroll
            for (int kc2 = 0; kc2 < 4; kc2++) {
                unsigned ap[4];
                ap[0] = pexp[2*kc2][0];
                ap[1] = pexp[2*kc2][1];
                ap[2] = pexp[2*kc2+1][0];
                ap[3] = pexp[2*kc2+1][1];
#pragma unroll
                for (int ntp = 0; ntp < 8; ntp++) {
                    unsigned bv[4];
                    int row = kc2 * 16 + (lane & 7) + (((lane >> 3) & 1) << 3);
                    int c2  = ntp * 2 + (lane >> 4);
                    ldsm4t(bv, smem_u32(Vc + row * FSTR + c2 * 8));
                    mma_f16(oacc[2*ntp],   ap, bv[0], bv[1]);
                    mma_f16(oacc[2*ntp+1], ap, bv[2], bv[3]);
                }
            }
        }

        float inv0 = 1.0f / l0s;
        float inv1 = 1.0f / l1s;
#pragma unroll
        for (int nt = 0; nt < 16; nt++) {
            int col = h * HDIM + nt * 8 + 2 * tig;
            *(__half2*)&O[(long)r0 * QSIZE + col] =
                __floats2half2_rn(oacc[nt][0] * inv0, oacc[nt][1] * inv0);
            *(__half2*)&O[(long)r1 * QSIZE + col] =
                __floats2half2_rn(oacc[nt][2] * inv1, oacc[nt][3] * inv1);
        }
    }
}

// =====================================================================
// launch
// =====================================================================
extern "C" void kernel_launch(void* const* d_in, const int* in_sizes, int n_in,
                              void* d_out, int out_size)
{
    const int*   positions = (const int*)d_in[0];
    const float* hidden    = (const float*)d_in[1];
    const float* wqkv      = (const float*)d_in[2];
    const float* wo        = (const float*)d_in[3];
    const float* qnw       = (const float*)d_in[4];
    const float* knw       = (const float*)d_in[5];
    float* out = (float*)d_out;

    __half *qkv16, *h16, *wqkv16, *wo16, *q16, *k16, *o16;
    cudaGetSymbolAddress((void**)&qkv16, g_qkv16);
    cudaGetSymbolAddress((void**)&h16, g_h16);
    cudaGetSymbolAddress((void**)&wqkv16, g_wqkv16);
    cudaGetSymbolAddress((void**)&wo16, g_wo16);
    cudaGetSymbolAddress((void**)&q16, g_q16);
    cudaGetSymbolAddress((void**)&k16, g_k16);
    cudaGetSymbolAddress((void**)&o16, g_o16);

    static bool attr_done = false;
    if (!attr_done) {
        cudaFuncSetAttribute(gemm_h16<__half>,
                             cudaFuncAttributeMaxDynamicSharedMemorySize, GEMM_SMEM);
        cudaFuncSetAttribute(gemm_h16<float>,
                             cudaFuncAttributeMaxDynamicSharedMemorySize, GEMM_SMEM);
        cudaFuncSetAttribute(flash_h16,
                             cudaFuncAttributeMaxDynamicSharedMemorySize, FLASH_SMEM);
        attr_done = true;
    }

    // 0) fp32 -> fp16 converts
    f2h_kernel<<<2048, 256>>>(hidden, h16, (long)T * HIDDEN);
    f2h_kernel<<<4096, 256>>>(wqkv, wqkv16, (long)QKVW * HIDDEN);
    f2h_kernel<<<4096, 256>>>(wo, wo16, (long)HIDDEN * QSIZE);

    // 1) qkv16 = hidden @ wqkv^T   [2048, 6144] fp16
    {
        dim3 grid(QKVW / 128, T / 128);
        gemm_h16<__half><<<grid, 256, GEMM_SMEM>>>(h16, wqkv16, qkv16, T, QKVW, HIDDEN);
    }
    // 2) rmsnorm + rope head-major repack (sincos shared across heads)
    {
        rmsnorm_rope_kernel<<<T, 512>>>(qkv16, positions, qnw, knw, q16, k16);
    }
    // 3) causal flash attention -> o16, balanced 296-CTA schedule
    {
        flash_h16<<<FGRID, 256, FLASH_SMEM>>>(q16, k16, qkv16, o16);
    }
    // 4) out = o @ wo^T   [2048, 2048] fp32
    {
        dim3 grid(HIDDEN / 128, T / 128);
        gemm_h16<float><<<grid, 256, GEMM_SMEM>>>(o16, wo16, out, T, HIDDEN, QSIZE);
    }
}

// round 14
// speedup vs baseline: 1.4882x; 1.4882x over previous
#include <cuda_runtime.h>
#include <cuda_fp16.h>
#include <math.h>

// ---------------- constants ----------------
#define T        2048
#define HIDDEN   2048
#define NHEADS   32
#define NKV      8
#define HDIM     128
#define QSIZE    (NHEADS * HDIM)          // 4096
#define KVSIZE   (NKV * HDIM)             // 1024
#define QKVW     (QSIZE + 2 * KVSIZE)     // 6144
#define SCALING  0.08838834764831845f     // 1/sqrt(128)
#define LOG2E    1.4426950408889634f
#define L2_10000_D64 0.20762050593046f    // log2(10000)/64

#define NQB      (T / 128)                // 16 q-tiles per head
#define NTILES   (NQB * NHEADS)           // 512
#define FGRID    296                      // 2 CTAs x 148 SMs

// ---------------- scratch (no allocations allowed) ----------------
__device__ __half g_qkv16[T * QKVW];           // fp16 qkv (gemm out)
__device__ __half g_h16[T * HIDDEN];           // hidden fp16
__device__ __half g_wqkv16[QKVW * HIDDEN];     // wqkv fp16
__device__ __half g_wo16[HIDDEN * QSIZE];      // wo fp16
__device__ __half g_q16[NHEADS * T * HDIM];    // head-major, scaled by 1/sqrt(D)*log2e
__device__ __half g_k16[NKV * T * HDIM];       // head-major
__device__ __half g_o16[T * QSIZE];            // attention out fp16

// ---------------- ptx helpers ----------------
__device__ __forceinline__ unsigned smem_u32(const void* p) {
    return (unsigned)__cvta_generic_to_shared(p);
}
__device__ __forceinline__ void ldsm4(unsigned r[4], unsigned addr) {
    asm volatile("ldmatrix.sync.aligned.m8n8.x4.shared.b16 {%0,%1,%2,%3},[%4];"
                 : "=r"(r[0]), "=r"(r[1]), "=r"(r[2]), "=r"(r[3]) : "r"(addr));
}
__device__ __forceinline__ void ldsm4t(unsigned r[4], unsigned addr) {
    asm volatile("ldmatrix.sync.aligned.m8n8.x4.trans.shared.b16 {%0,%1,%2,%3},[%4];"
                 : "=r"(r[0]), "=r"(r[1]), "=r"(r[2]), "=r"(r[3]) : "r"(addr));
}
__device__ __forceinline__ void mma_f16(float c[4], const unsigned a[4],
                                        unsigned b0, unsigned b1) {
    asm volatile("mma.sync.aligned.m16n8k16.row.col.f32.f16.f16.f32 "
                 "{%0,%1,%2,%3},{%4,%5,%6,%7},{%8,%9},{%0,%1,%2,%3};"
                 : "+f"(c[0]), "+f"(c[1]), "+f"(c[2]), "+f"(c[3])
                 : "r"(a[0]), "r"(a[1]), "r"(a[2]), "r"(a[3]), "r"(b0), "r"(b1));
}
__device__ __forceinline__ void cp16(unsigned saddr, const void* g) {
    asm volatile("cp.async.cg.shared.global [%0],[%1],16;" :: "r"(saddr), "l"(g));
}
__device__ __forceinline__ void cp_commit() {
    asm volatile("cp.async.commit_group;");
}
template <int N>
__device__ __forceinline__ void cp_wait() {
    asm volatile("cp.async.wait_group %0;" :: "n"(N));
}
__device__ __forceinline__ unsigned pack_h2(float a, float b) {
    __half2 h = __floats2half2_rn(a, b);
    return *reinterpret_cast<unsigned*>(&h);
}
// two exps in one MUFU op; result is the packed fp16 pair for the PV MMA
__device__ __forceinline__ unsigned h2exp2(unsigned x) {
    unsigned r;
    asm("ex2.approx.f16x2 %0, %1;" : "=r"(r) : "r"(x));
    return r;
}

// =====================================================================
// fused fp32 -> fp16 convert for hidden + wqkv + wo (one launch)
// =====================================================================
#define N_H   ((long)T * HIDDEN)           // 4194304
#define N_WQ  ((long)QKVW * HIDDEN)        // 12582912
#define N_WO  ((long)HIDDEN * QSIZE)       // 8388608
#define N_ALL (N_H + N_WQ + N_WO)          // 25165824 (6291456 float4)

__global__ void f2h_all_kernel(const float* __restrict__ hid,
                               const float* __restrict__ wqkv,
                               const float* __restrict__ wo,
                               __half* __restrict__ h16,
                               __half* __restrict__ wqkv16,
                               __half* __restrict__ wo16)
{
    long i = ((long)blockIdx.x * blockDim.x + threadIdx.x) * 4;
    long stride = (long)gridDim.x * blockDim.x * 4;
    for (; i < N_ALL; i += stride) {
        const float* src;
        __half* dst;
        long off;
        if (i < N_H)            { src = hid;  dst = h16;    off = i; }
        else if (i < N_H + N_WQ){ src = wqkv; dst = wqkv16; off = i - N_H; }
        else                    { src = wo;   dst = wo16;   off = i - N_H - N_WQ; }
        float4 v = *(const float4*)(src + off);
        *(__half2*)(dst + off)     = __floats2half2_rn(v.x, v.y);
        *(__half2*)(dst + off + 2) = __floats2half2_rn(v.z, v.w);
    }
}

// =====================================================================
// fp16 tensor-core GEMM (measured-best config, R12):
// C[M,N] = A[M,K](h) * B[N,K](h)^T. 128x128 block, BK=64,
// 3-stage cp.async pipeline, 256 threads, 2 CTAs/SM.
// =====================================================================
#define GSTRH 72
#define STAGE_H (256 * GSTRH)             // halves per stage (A128 + B128 rows)
#define GS 3
#define GEMM_SMEM (GS * STAGE_H * 2)      // 110592 B

template <typename OutT>
__global__ __launch_bounds__(256, 2) void gemm_h16(
    const __half* __restrict__ A, const __half* __restrict__ B,
    OutT* __restrict__ C, int M, int N, int K)
{
    extern __shared__ __half smh[];

    int tid = threadIdx.x;
    int lane = tid & 31, warp = tid >> 5;
    int gid = lane >> 2, tig = lane & 3;
    int wm = warp >> 2, wn = warp & 3;
    int m0 = blockIdx.y * 128, n0 = blockIdx.x * 128;

    int ch   = tid & 7;        // 16B chunk (8 halves)
    int row0 = tid >> 3;       // 0..31
    const __half* gsrc[8];
#pragma unroll
    for (int i = 0; i < 8; i++) {
        int row = row0 + 32 * i;
        gsrc[i] = (row < 128 ? A + (long)(m0 + row) * K
                             : B + (long)(n0 + row - 128) * K) + ch * 8;
    }
    unsigned sdst[8];
#pragma unroll
    for (int i = 0; i < 8; i++)
        sdst[i] = smem_u32(smh + (row0 + 32 * i) * GSTRH + ch * 8);

    float acc[4][4][4];
#pragma unroll
    for (int mt = 0; mt < 4; mt++)
#pragma unroll
        for (int nt = 0; nt < 4; nt++)
#pragma unroll
            for (int r = 0; r < 4; r++) acc[mt][nt][r] = 0.f;

    int nk = K >> 6;   // 64-wide k tiles

    // prologue: stages 0, 1
#pragma unroll
    for (int s = 0; s < 2; s++) {
#pragma unroll
        for (int i = 0; i < 8; i++)
            cp16(sdst[i] + s * (STAGE_H * 2), gsrc[i] + (long)s * 64);
        cp_commit();
    }

    for (int k = 0; k < nk; k++) {
        cp_wait<1>();
        __syncthreads();

        if (k + 2 < nk) {
            int sb = ((k + 2) % GS) * (STAGE_H * 2);
            long kof = (long)(k + 2) * 64;
#pragma unroll
            for (int i = 0; i < 8; i++)
                cp16(sdst[i] + sb, gsrc[i] + kof);
        }
        cp_commit();

        const __half* Ac = smh + (k % GS) * STAGE_H;
        const __half* Bc = Ac + 128 * GSTRH;
#pragma unroll
        for (int kc = 0; kc < 4; kc++) {
            unsigned aq[4][4], bk[2][4];
#pragma unroll
            for (int mt = 0; mt < 4; mt++) {
                int row = wm * 64 + mt * 16 + (lane & 15);
                int c2  = kc * 2 + (lane >> 4);
                ldsm4(aq[mt], smem_u32(Ac + row * GSTRH + c2 * 8));
            }
#pragma unroll
            for (int ntp = 0; ntp < 2; ntp++) {
                int row = wn * 32 + ntp * 16 + (lane & 7) + ((lane >> 4) << 3);
                int c2  = kc * 2 + ((lane >> 3) & 1);
                ldsm4(bk[ntp], smem_u32(Bc + row * GSTRH + c2 * 8));
            }
#pragma unroll
            for (int mt = 0; mt < 4; mt++)
#pragma unroll
                for (int ntp = 0; ntp < 2; ntp++) {
                    mma_f16(acc[mt][2*ntp],   aq[mt], bk[ntp][0], bk[ntp][1]);
                    mma_f16(acc[mt][2*ntp+1], aq[mt], bk[ntp][2], bk[ntp][3]);
                }
        }
        // single barrier per iter (top of loop)
    }

    // epilogue
#pragma unroll
    for (int mt = 0; mt < 4; mt++) {
        int row = m0 + wm * 64 + mt * 16 + gid;
#pragma unroll
        for (int nt = 0; nt < 4; nt++) {
            int col = n0 + wn * 32 + nt * 8 + 2 * tig;
            if (sizeof(OutT) == 4) {
                *(float2*)&((float*)C)[(long)row * N + col] =
                    make_float2(acc[mt][nt][0], acc[mt][nt][1]);
                *(float2*)&((float*)C)[(long)(row + 8) * N + col] =
                    make_float2(acc[mt][nt][2], acc[mt][nt][3]);
            } else {
                *(__half2*)&((__half*)C)[(long)row * N + col] =
                    __floats2half2_rn(acc[mt][nt][0], acc[mt][nt][1]);
                *(__half2*)&((__half*)C)[(long)(row + 8) * N + col] =
                    __floats2half2_rn(acc[mt][nt][2], acc[mt][nt][3]);
            }
        }
    }
}

// =====================================================================
// Fused per-head RMSNorm + RoPE. One block per t, 1024 threads =
// 8 head-slots x 128 -> 5 sequential iterations (half the barriers).
// sincos table computed ONCE per t into smem.
// =====================================================================
__global__ __launch_bounds__(1024) void rmsnorm_rope_kernel(
    const __half* __restrict__ qkv, const int* __restrict__ positions,
    const float* __restrict__ qw, const float* __restrict__ kw,
    __half* __restrict__ q16, __half* __restrict__ k16)
{
    int t   = blockIdx.x;
    int tid = threadIdx.x;
    int g   = tid >> 7;            // head slot 0..7
    int d   = tid & 127;           // 0..127
    int lane = d & 31, wp = d >> 5;

    __shared__ float scos[64], ssin[64];
    __shared__ float sred[8][4];
    __shared__ float snorm[8];
    __shared__ float sx[8][HDIM];

    if (tid < 64) {
        float pos  = (float)positions[t];
        float invf = exp2f(-(float)tid * L2_10000_D64);
        float ang  = pos * invf;
        float c, s;
        sincosf(ang, &s, &c);
        scos[tid] = c;
        ssin[tid] = s;
    }
    __syncthreads();

#pragma unroll
    for (int iter = 0; iter < 5; iter++) {
        int hh = iter * 8 + g;     // 0..39
        bool isq = (hh < NHEADS);
        int off = isq ? hh * HDIM : QSIZE + (hh - NHEADS) * HDIM;
        const float* w = isq ? qw : kw;
        const __half* x = qkv + (long)t * QKVW + off;
        __half* outp = isq ? (q16 + ((long)hh * T + t) * HDIM)
                           : (k16 + ((long)(hh - NHEADS) * T + t) * HDIM);
        float oscale = isq ? SCALING * LOG2E : 1.0f;

        float v = __half2float(x[d]);
        float ss = v * v;
#pragma unroll
        for (int o = 16; o >= 1; o >>= 1)
            ss += __shfl_xor_sync(0xffffffffu, ss, o);
        if (lane == 0) sred[g][wp] = ss;
        __syncthreads();
        if (d == 0) {
            float tot = sred[g][0] + sred[g][1] + sred[g][2] + sred[g][3];
            snorm[g] = rsqrtf(tot / (float)HDIM + 1e-6f);
        }
        __syncthreads();

        float nv = v * snorm[g] * w[d];
        sx[g][d] = nv;
        __syncthreads();

        if (d < 64) {
            float x1 = sx[g][d];
            float x2 = sx[g][d + 64];
            float c = scos[d], s = ssin[d];
            outp[d]      = __float2half_rn((x1 * c - x2 * s) * oscale);
            outp[d + 64] = __float2half_rn((x2 * c + x1 * s) * oscale);
        }
        __syncthreads();   // protect sx/sred for next iter
    }
}

// =====================================================================
// fp16 flash attention (causal, GQA). Output fp16.
// Balanced 296-CTA schedule (2/SM), antipodal two-tile pairing,
// diagonal warp-skip, ex2.approx.f16x2 softmax, predicated rescale.
// =====================================================================
#define FSTR 136
#define FQ_H (128 * FSTR)
#define FKV_H (64 * FSTR)
#define FLASH_SMEM ((FQ_H + 4 * FKV_H) * 2)   // 104448 B

__global__ __launch_bounds__(256, 2) void flash_h16(
    const __half* __restrict__ Q, const __half* __restrict__ Kh,
    const __half* __restrict__ qkv16, __half* __restrict__ O)
{
    extern __shared__ __half smf[];
    __half* Qs = smf;                 // [128][136]
    __half* Ks = smf + FQ_H;          // [2][64][136]
    __half* Vs = Ks + 2 * FKV_H;      // [2][64][136]

    int cta = blockIdx.x;             // 0..295
    int tid = threadIdx.x;
    int lane = tid & 31, warp = tid >> 5;
    int gid = lane >> 2, tig = lane & 3;

    for (int ti = 0; ti < 2; ti++) {
        int t;
        if (ti == 0) {
            t = cta;                          // tiles 0..295 (big half)
        } else {
            if (cta < 80) break;              // no second tile
            t = (NTILES - 1) - (cta - 80);    // cta=80 -> 511, cta=295 -> 296
        }
        int qb = (NQB - 1) - (t >> 5);        // descending work order
        int h  = t & 31;
        int kvh = h >> 2;
        int q0 = qb * 128;

        const __half* Qg = Q + ((long)h * T + q0) * HDIM;
        const __half* Kg = Kh + (long)kvh * T * HDIM;
        const __half* Vg = qkv16 + QSIZE + KVSIZE + kvh * HDIM;   // + t*QKVW

        __syncthreads();   // smem from previous tile fully consumed

        // prologue: Q tile + KV block 0
#pragma unroll
        for (int i = 0; i < 8; i++) {
            int idx = tid + i * 256;
            int r = idx >> 4, c = idx & 15;
            cp16(smem_u32(Qs + r * FSTR + c * 8), Qg + r * HDIM + c * 8);
        }
#pragma unroll
        for (int i = 0; i < 4; i++) {
            int idx = tid + i * 256;
            int r = idx >> 4, c = idx & 15;
            cp16(smem_u32(Ks + r * FSTR + c * 8), Kg + (long)r * HDIM + c * 8);
            cp16(smem_u32(Vs + r * FSTR + c * 8), Vg + (long)r * QKVW + c * 8);
        }
        cp_commit();

        float m0s = -1e30f, m1s = -1e30f, l0s = 0.f, l1s = 0.f;
        float oacc[16][4];
#pragma unroll
        for (int nt = 0; nt < 16; nt++)
#pragma unroll
            for (int r = 0; r < 4; r++) oacc[nt][r] = 0.f;

        int r0 = q0 + warp * 16 + gid;
        int r1 = r0 + 8;
        int kbmax = 2 * qb + 1;

        for (int kb = 0; kb <= kbmax; kb++) {
            cp_wait<0>();
            __syncthreads();

            if (kb < kbmax) {
                __half* Kn = Ks + ((kb + 1) & 1) * FKV_H;
                __half* Vn = Vs + ((kb + 1) & 1) * FKV_H;
                long rowoff = (long)(kb + 1) * 64;
#pragma unroll
                for (int i = 0; i < 4; i++) {
                    int idx = tid + i * 256;
                    int r = idx >> 4, c = idx & 15;
                    cp16(smem_u32(Kn + r * FSTR + c * 8), Kg + (rowoff + r) * HDIM + c * 8);
                    cp16(smem_u32(Vn + r * FSTR + c * 8), Vg + (rowoff + r) * QKVW + c * 8);
                }
            }
            cp_commit();

            // diagonal half-block: warps 0-3 fully masked -> exact skip
            if (kb == kbmax && warp < 4) continue;

            const __half* Kc = Ks + (kb & 1) * FKV_H;
            const __half* Vc = Vs + (kb & 1) * FKV_H;

            // ---- S = Q K^T ----
            float sacc[8][4];
#pragma unroll
            for (int nt = 0; nt < 8; nt++)
#pragma unroll
                for (int r = 0; r < 4; r++) sacc[nt][r] = 0.f;

#pragma unroll
            for (int kc = 0; kc < 8; kc++) {
                unsigned aq[4];
                {
                    int row = warp * 16 + (lane & 15);
                    int c2  = kc * 2 + (lane >> 4);
                    ldsm4(aq, smem_u32(Qs + row * FSTR + c2 * 8));
                }
#pragma unroll
                for (int ntp = 0; ntp < 4; ntp++) {
                    unsigned bk[4];
                    int row = ntp * 16 + (lane & 7) + ((lane >> 4) << 3);
                    int c2  = kc * 2 + ((lane >> 3) & 1);
                    ldsm4(bk, smem_u32(Kc + row * FSTR + c2 * 8));
                    mma_f16(sacc[2*ntp],   aq, bk[0], bk[1]);
                    mma_f16(sacc[2*ntp+1], aq, bk[2], bk[3]);
                }
            }

            // ---- causal mask (last two kv blocks only) ----
            if (kb >= 2 * qb) {
#pragma unroll
                for (int nt = 0; nt < 8; nt++) {
                    int colb = kb * 64 + nt * 8 + 2 * tig;
                    if (colb > r0)     sacc[nt][0] = -1e30f;
                    if (colb + 1 > r0) sacc[nt][1] = -1e30f;
                    if (colb > r1)     sacc[nt][2] = -1e30f;
                    if (colb + 1 > r1) sacc[nt][3] = -1e30f;
                }
            }

            // ---- online softmax (fp16x2 exps, predicated rescale) ----
            float mx0 = -1e30f, mx1 = -1e30f;
#pragma unroll
            for (int nt = 0; nt < 8; nt++) {
                mx0 = fmaxf(mx0, fmaxf(sacc[nt][0], sacc[nt][1]));
                mx1 = fmaxf(mx1, fmaxf(sacc[nt][2], sacc[nt][3]));
            }
            mx0 = fmaxf(mx0, __shfl_xor_sync(0xffffffffu, mx0, 1));
            mx0 = fmaxf(mx0, __shfl_xor_sync(0xffffffffu, mx0, 2));
            mx1 = fmaxf(mx1, __shfl_xor_sync(0xffffffffu, mx1, 1));
            mx1 = fmaxf(mx1, __shfl_xor_sync(0xffffffffu, mx1, 2));

            float mn0 = fmaxf(m0s, mx0);
            float mn1 = fmaxf(m1s, mx1);
            bool rescale = (mn0 > m0s) || (mn1 > m1s);

            unsigned pexp[8][2];
            float ls0 = 0.f, ls1 = 0.f;
#pragma unroll
            for (int nt = 0; nt < 8; nt++) {
                unsigned e01 = h2exp2(pack_h2(sacc[nt][0] - mn0, sacc[nt][1] - mn0));
                unsigned e23 = h2exp2(pack_h2(sacc[nt][2] - mn1, sacc[nt][3] - mn1));
                pexp[nt][0] = e01;
                pexp[nt][1] = e23;
                float2 f01 = __half22float2(*reinterpret_cast<__half2*>(&e01));
                float2 f23 = __half22float2(*reinterpret_cast<__half2*>(&e23));
                ls0 += f01.x + f01.y;
                ls1 += f23.x + f23.y;
            }
            ls0 += __shfl_xor_sync(0xffffffffu, ls0, 1);
            ls0 += __shfl_xor_sync(0xffffffffu, ls0, 2);
            ls1 += __shfl_xor_sync(0xffffffffu, ls1, 1);
            ls1 += __shfl_xor_sync(0xffffffffu, ls1, 2);

            if (rescale) {
                float corr0 = exp2f(m0s - mn0);
                float corr1 = exp2f(m1s - mn1);
                l0s = l0s * corr0 + ls0;
                l1s = l1s * corr1 + ls1;
#pragma unroll
                for (int nt = 0; nt < 16; nt++) {
                    oacc[nt][0] *= corr0;
                    oacc[nt][1] *= corr0;
                    oacc[nt][2] *= corr1;
                    oacc[nt][3] *= corr1;
                }
                m0s = mn0;
                m1s = mn1;
            } else {
                l0s += ls0;
                l1s += ls1;
            }

            // ---- O += P V (P fragments come straight from h2exp2) ----
#pragma unroll
            for (int kc2 = 0; kc2 < 4; kc2++) {
                unsigned ap[4];
                ap[0] = pexp[2*kc2][0];
                ap[1] = pexp[2*kc2][1];
                ap[2] = pexp[2*kc2+1][0];
                ap[3] = pexp[2*kc2+1][1];
#pragma unroll
                for (int ntp = 0; ntp < 8; ntp++) {
                    unsigned bv[4];
                    int row = kc2 * 16 + (lane & 7) + (((lane >> 3) & 1) << 3);
                    int c2  = ntp * 2 + (lane >> 4);
                    ldsm4t(bv, smem_u32(Vc + row * FSTR + c2 * 8));
                    mma_f16(oacc[2*ntp],   ap, bv[0], bv[1]);
                    mma_f16(oacc[2*ntp+1], ap, bv[2], bv[3]);
                }
            }
        }

        float inv0 = 1.0f / l0s;
        float inv1 = 1.0f / l1s;
#pragma unroll
        for (int nt = 0; nt < 16; nt++) {
            int col = h * HDIM + nt * 8 + 2 * tig;
            *(__half2*)&O[(long)r0 * QSIZE + col] =
                __floats2half2_rn(oacc[nt][0] * inv0, oacc[nt][1] * inv0);
            *(__half2*)&O[(long)r1 * QSIZE + col] =
                __floats2half2_rn(oacc[nt][2] * inv1, oacc[nt][3] * inv1);
        }
    }
}

// =====================================================================
// launch
// =====================================================================
extern "C" void kernel_launch(void* const* d_in, const int* in_sizes, int n_in,
                              void* d_out, int out_size)
{
    const int*   positions = (const int*)d_in[0];
    const float* hidden    = (const float*)d_in[1];
    const float* wqkv      = (const float*)d_in[2];
    const float* wo        = (const float*)d_in[3];
    const float* qnw       = (const float*)d_in[4];
    const float* knw       = (const float*)d_in[5];
    float* out = (float*)d_out;

    __half *qkv16, *h16, *wqkv16, *wo16, *q16, *k16, *o16;
    cudaGetSymbolAddress((void**)&qkv16, g_qkv16);
    cudaGetSymbolAddress((void**)&h16, g_h16);
    cudaGetSymbolAddress((void**)&wqkv16, g_wqkv16);
    cudaGetSymbolAddress((void**)&wo16, g_wo16);
    cudaGetSymbolAddress((void**)&q16, g_q16);
    cudaGetSymbolAddress((void**)&k16, g_k16);
    cudaGetSymbolAddress((void**)&o16, g_o16);

    static bool attr_done = false;
    if (!attr_done) {
        cudaFuncSetAttribute(gemm_h16<__half>,
                             cudaFuncAttributeMaxDynamicSharedMemorySize, GEMM_SMEM);
        cudaFuncSetAttribute(gemm_h16<float>,
                             cudaFuncAttributeMaxDynamicSharedMemorySize, GEMM_SMEM);
        cudaFuncSetAttribute(flash_h16,
                             cudaFuncAttributeMaxDynamicSharedMemorySize, FLASH_SMEM);
        attr_done = true;
    }

    // 0) fused fp32 -> fp16 converts (hidden + wqkv + wo, one launch)
    f2h_all_kernel<<<4096, 256>>>(hidden, wqkv, wo, h16, wqkv16, wo16);

    // 1) qkv16 = hidden @ wqkv^T   [2048, 6144] fp16
    {
        dim3 grid(QKVW / 128, T / 128);
        gemm_h16<__half><<<grid, 256, GEMM_SMEM>>>(h16, wqkv16, qkv16, T, QKVW, HIDDEN);
    }
    // 2) rmsnorm + rope head-major repack (8 head-slots, 5 iters)
    {
        rmsnorm_rope_kernel<<<T, 1024>>>(qkv16, positions, qnw, knw, q16, k16);
    }
    // 3) causal flash attention -> o16, balanced 296-CTA schedule
    {
        flash_h16<<<FGRID, 256, FLASH_SMEM>>>(q16, k16, qkv16, o16);
    }
    // 4) out = o @ wo^T   [2048, 2048] fp32
    {
        dim3 grid(HIDDEN / 128, T / 128);
        gemm_h16<float><<<grid, 256, GEMM_SMEM>>>(o16, wo16, out, T, HIDDEN, QSIZE);
    }
}

// round 15
// speedup vs baseline: 1.5439x; 1.0375x over previous
#include <cuda_runtime.h>
#include <cuda_fp16.h>
#include <math.h>

// ---------------- constants ----------------
#define T        2048
#define HIDDEN   2048
#define NHEADS   32
#define NKV      8
#define HDIM     128
#define QSIZE    (NHEADS * HDIM)          // 4096
#define KVSIZE   (NKV * HDIM)             // 1024
#define QKVW     (QSIZE + 2 * KVSIZE)     // 6144
#define SCALING  0.08838834764831845f     // 1/sqrt(128)
#define LOG2E    1.4426950408889634f
#define L2_10000_D64 0.20762050593046f    // log2(10000)/64

#define NQB      (T / 128)                // 16 q-tiles per head
#define NTILES   (NQB * NHEADS)           // 512
#define FGRID    296                      // 2 CTAs x 148 SMs

// ---------------- scratch (no allocations allowed) ----------------
__device__ __half g_h16[T * HIDDEN];           // hidden fp16
__device__ __half g_wqkv16[QKVW * HIDDEN];     // wqkv fp16
__device__ __half g_wo16[HIDDEN * QSIZE];      // wo fp16
__device__ __half g_q16[NHEADS * T * HDIM];    // head-major, scaled by 1/sqrt(D)*log2e
__device__ __half g_k16[NKV * T * HDIM];       // head-major
__device__ __half g_v16[NKV * T * HDIM];       // head-major
__device__ __half g_o16[T * QSIZE];            // attention out fp16
__device__ float  g_cos[T * 64];               // rope tables
__device__ float  g_sin[T * 64];

// ---------------- ptx helpers ----------------
__device__ __forceinline__ unsigned smem_u32(const void* p) {
    return (unsigned)__cvta_generic_to_shared(p);
}
__device__ __forceinline__ void ldsm4(unsigned r[4], unsigned addr) {
    asm volatile("ldmatrix.sync.aligned.m8n8.x4.shared.b16 {%0,%1,%2,%3},[%4];"
                 : "=r"(r[0]), "=r"(r[1]), "=r"(r[2]), "=r"(r[3]) : "r"(addr));
}
__device__ __forceinline__ void ldsm4t(unsigned r[4], unsigned addr) {
    asm volatile("ldmatrix.sync.aligned.m8n8.x4.trans.shared.b16 {%0,%1,%2,%3},[%4];"
                 : "=r"(r[0]), "=r"(r[1]), "=r"(r[2]), "=r"(r[3]) : "r"(addr));
}
__device__ __forceinline__ void mma_f16(float c[4], const unsigned a[4],
                                        unsigned b0, unsigned b1) {
    asm volatile("mma.sync.aligned.m16n8k16.row.col.f32.f16.f16.f32 "
                 "{%0,%1,%2,%3},{%4,%5,%6,%7},{%8,%9},{%0,%1,%2,%3};"
                 : "+f"(c[0]), "+f"(c[1]), "+f"(c[2]), "+f"(c[3])
                 : "r"(a[0]), "r"(a[1]), "r"(a[2]), "r"(a[3]), "r"(b0), "r"(b1));
}
__device__ __forceinline__ void cp16(unsigned saddr, const void* g) {
    asm volatile("cp.async.cg.shared.global [%0],[%1],16;" :: "r"(saddr), "l"(g));
}
__device__ __forceinline__ void cp_commit() {
    asm volatile("cp.async.commit_group;");
}
template <int N>
__device__ __forceinline__ void cp_wait() {
    asm volatile("cp.async.wait_group %0;" :: "n"(N));
}
__device__ __forceinline__ unsigned pack_h2(float a, float b) {
    __half2 h = __floats2half2_rn(a, b);
    return *reinterpret_cast<unsigned*>(&h);
}
// two exps in one MUFU op; result is the packed fp16 pair for the PV MMA
__device__ __forceinline__ unsigned h2exp2(unsigned x) {
    unsigned r;
    asm("ex2.approx.f16x2 %0, %1;" : "=r"(r) : "r"(x));
    return r;
}

// =====================================================================
// fused fp32 -> fp16 convert for hidden + wqkv + wo (one launch)
// =====================================================================
#define N_H   ((long)T * HIDDEN)
#define N_WQ  ((long)QKVW * HIDDEN)
#define N_WO  ((long)HIDDEN * QSIZE)
#define N_ALL (N_H + N_WQ + N_WO)

__global__ void f2h_all_kernel(const float* __restrict__ hid,
                               const float* __restrict__ wqkv,
                               const float* __restrict__ wo,
                               __half* __restrict__ h16,
                               __half* __restrict__ wqkv16,
                               __half* __restrict__ wo16)
{
    long i = ((long)blockIdx.x * blockDim.x + threadIdx.x) * 4;
    long stride = (long)gridDim.x * blockDim.x * 4;
    for (; i < N_ALL; i += stride) {
        const float* src;
        __half* dst;
        long off;
        if (i < N_H)            { src = hid;  dst = h16;    off = i; }
        else if (i < N_H + N_WQ){ src = wqkv; dst = wqkv16; off = i - N_H; }
        else                    { src = wo;   dst = wo16;   off = i - N_H - N_WQ; }
        float4 v = *(const float4*)(src + off);
        *(__half2*)(dst + off)     = __floats2half2_rn(v.x, v.y);
        *(__half2*)(dst + off + 2) = __floats2half2_rn(v.z, v.w);
    }
}

// =====================================================================
// rope table: cos/sin per (t, d<64)
// =====================================================================
__global__ void rope_table_kernel(const int* __restrict__ positions,
                                  float* __restrict__ gcos,
                                  float* __restrict__ gsin)
{
    int i = blockIdx.x * blockDim.x + threadIdx.x;   // 0 .. T*64-1
    int t = i >> 6, d = i & 63;
    float ang = (float)positions[t] * exp2f(-(float)d * L2_10000_D64);
    float c, s;
    sincosf(ang, &s, &c);
    gcos[i] = c;
    gsin[i] = s;
}

// =====================================================================
// GEMM mainloop config (measured-best): 128x128 block, BK=64,
// 3-stage cp.async pipeline, 256 threads, 2 CTAs/SM.
// =====================================================================
#define GSTRH 72
#define STAGE_H (256 * GSTRH)
#define GS 3
#define GEMM_SMEM (GS * STAGE_H * 2)      // 110592 B

// ---- mainloop as a macro-like inline: produces acc[4][4][4] ----
#define GEMM_MAINLOOP(A, B, K)                                               \
    int ch   = tid & 7;                                                      \
    int row0 = tid >> 3;                                                     \
    const __half* gsrc[8];                                                   \
    _Pragma("unroll")                                                        \
    for (int i = 0; i < 8; i++) {                                            \
        int row = row0 + 32 * i;                                             \
        gsrc[i] = (row < 128 ? (A) + (long)(m0 + row) * (K)                  \
                             : (B) + (long)(n0 + row - 128) * (K)) + ch * 8; \
    }                                                                        \
    unsigned sdst[8];                                                        \
    _Pragma("unroll")                                                        \
    for (int i = 0; i < 8; i++)                                              \
        sdst[i] = smem_u32(smh + (row0 + 32 * i) * GSTRH + ch * 8);          \
    _Pragma("unroll")                                                        \
    for (int mt = 0; mt < 4; mt++)                                           \
        _Pragma("unroll")                                                    \
        for (int nt = 0; nt < 4; nt++)                                       \
            _Pragma("unroll")                                                \
            for (int r = 0; r < 4; r++) acc[mt][nt][r] = 0.f;                \
    int nk = (K) >> 6;                                                       \
    _Pragma("unroll")                                                        \
    for (int s = 0; s < 2; s++) {                                            \
        _Pragma("unroll")                                                    \
        for (int i = 0; i < 8; i++)                                          \
            cp16(sdst[i] + s * (STAGE_H * 2), gsrc[i] + (long)s * 64);       \
        cp_commit();                                                         \
    }                                                                        \
    for (int k = 0; k < nk; k++) {                                           \
        cp_wait<1>();                                                        \
        __syncthreads();                                                     \
        if (k + 2 < nk) {                                                    \
            int sb = ((k + 2) % GS) * (STAGE_H * 2);                         \
            long kof = (long)(k + 2) * 64;                                   \
            _Pragma("unroll")                                                \
            for (int i = 0; i < 8; i++)                                      \
                cp16(sdst[i] + sb, gsrc[i] + kof);                           \
        }                                                                    \
        cp_commit();                                                         \
        const __half* Ac = smh + (k % GS) * STAGE_H;                         \
        const __half* Bc = Ac + 128 * GSTRH;                                 \
        _Pragma("unroll")                                                    \
        for (int kc = 0; kc < 4; kc++) {                                     \
            unsigned aq[4][4], bk[2][4];                                     \
            _Pragma("unroll")                                                \
            for (int mt = 0; mt < 4; mt++) {                                 \
                int row = wm * 64 + mt * 16 + (lane & 15);                   \
                int c2  = kc * 2 + (lane >> 4);                              \
                ldsm4(aq[mt], smem_u32(Ac + row * GSTRH + c2 * 8));          \
            }                                                                \
            _Pragma("unroll")                                                \
            for (int ntp = 0; ntp < 2; ntp++) {                              \
                int row = wn * 32 + ntp * 16 + (lane & 7) + ((lane >> 4) << 3); \
                int c2  = kc * 2 + ((lane >> 3) & 1);                        \
                ldsm4(bk[ntp], smem_u32(Bc + row * GSTRH + c2 * 8));         \
            }                                                                \
            _Pragma("unroll")                                                \
            for (int mt = 0; mt < 4; mt++)                                   \
                _Pragma("unroll")                                            \
                for (int ntp = 0; ntp < 2; ntp++) {                          \
                    mma_f16(acc[mt][2*ntp],   aq[mt], bk[ntp][0], bk[ntp][1]); \
                    mma_f16(acc[mt][2*ntp+1], aq[mt], bk[ntp][2], bk[ntp][3]); \
                }                                                            \
        }                                                                    \
    }

// =====================================================================
// QKV GEMM with FUSED RMSNorm + RoPE + head-major fp16 repack.
// N-tile (128 cols) == one head. q heads: bx 0..31, k: 32..39, v: 40..47.
// =====================================================================
__global__ __launch_bounds__(256, 2) void gemm_qkv_fused(
    const __half* __restrict__ A, const __half* __restrict__ B,
    __half* __restrict__ q16, __half* __restrict__ k16, __half* __restrict__ v16,
    const float* __restrict__ gcos, const float* __restrict__ gsin,
    const float* __restrict__ qw, const float* __restrict__ kw)
{
    extern __shared__ __half smh[];

    int tid = threadIdx.x;
    int lane = tid & 31, warp = tid >> 5;
    int gid = lane >> 2, tig = lane & 3;
    int wm = warp >> 2, wn = warp & 3;
    int m0 = blockIdx.y * 128, n0 = blockIdx.x * 128;
    int bx = blockIdx.x;

    float acc[4][4][4];
    GEMM_MAINLOOP(A, B, HIDDEN)

    __syncthreads();   // mainloop smem fully consumed by all warps

    if (bx >= NHEADS + NKV) {
        // ---- v head: plain head-major fp16 write ----
        __half* vout = v16 + ((long)(bx - NHEADS - NKV) * T + m0) * HDIM;
#pragma unroll
        for (int mt = 0; mt < 4; mt++) {
            int rl = wm * 64 + mt * 16 + gid;
#pragma unroll
            for (int nt = 0; nt < 4; nt++) {
                int col = wn * 32 + nt * 8 + 2 * tig;
                *(__half2*)&vout[(long)rl * HDIM + col] =
                    __floats2half2_rn(acc[mt][nt][0], acc[mt][nt][1]);
                *(__half2*)&vout[(long)(rl + 8) * HDIM + col] =
                    __floats2half2_rn(acc[mt][nt][2], acc[mt][nt][3]);
            }
        }
        return;
    }

    // ---- q/k head: fused RMSNorm + RoPE ----
    float* sx    = (float*)smh;            // [128][130]  normalized*w tile
    float* part  = sx + 128 * 130;         // [128][4]    cross-warp ssq partials
    float* norml = part + 128 * 4;         // [128]       rsqrt factors

    // per-thread sum of squares for its 8 cols of each row
    float ssq0[4], ssq1[4];
#pragma unroll
    for (int mt = 0; mt < 4; mt++) {
        float a0 = 0.f, a1 = 0.f;
#pragma unroll
        for (int nt = 0; nt < 4; nt++) {
            a0 += acc[mt][nt][0] * acc[mt][nt][0] + acc[mt][nt][1] * acc[mt][nt][1];
            a1 += acc[mt][nt][2] * acc[mt][nt][2] + acc[mt][nt][3] * acc[mt][nt][3];
        }
        // reduce over tig (4 lanes) -> warp's 32-col partial
        a0 += __shfl_xor_sync(0xffffffffu, a0, 1);
        a0 += __shfl_xor_sync(0xffffffffu, a0, 2);
        a1 += __shfl_xor_sync(0xffffffffu, a1, 1);
        a1 += __shfl_xor_sync(0xffffffffu, a1, 2);
        ssq0[mt] = a0;
        ssq1[mt] = a1;
    }
    if (tig == 0) {
#pragma unroll
        for (int mt = 0; mt < 4; mt++) {
            int rl = wm * 64 + mt * 16 + gid;
            part[rl * 4 + wn] = ssq0[mt];
            part[(rl + 8) * 4 + wn] = ssq1[mt];
        }
    }
    __syncthreads();

    if (tid < 128) {
        float tot = part[tid * 4] + part[tid * 4 + 1] + part[tid * 4 + 2] + part[tid * 4 + 3];
        norml[tid] = rsqrtf(tot * (1.0f / (float)HDIM) + 1e-6f);
    }
    __syncthreads();

    // stage normalized * w
    const float* w = (bx < NHEADS) ? qw : kw;
#pragma unroll
    for (int mt = 0; mt < 4; mt++) {
        int rl = wm * 64 + mt * 16 + gid;
        float nv0 = norml[rl], nv1 = norml[rl + 8];
#pragma unroll
        for (int nt = 0; nt < 4; nt++) {
            int col = wn * 32 + nt * 8 + 2 * tig;
            float w0 = w[col], w1 = w[col + 1];
            sx[rl * 130 + col]           = acc[mt][nt][0] * nv0 * w0;
            sx[rl * 130 + col + 1]       = acc[mt][nt][1] * nv0 * w1;
            sx[(rl + 8) * 130 + col]     = acc[mt][nt][2] * nv1 * w0;
            sx[(rl + 8) * 130 + col + 1] = acc[mt][nt][3] * nv1 * w1;
        }
    }
    __syncthreads();

    // rope + head-major fp16 write
    float oscale = (bx < NHEADS) ? SCALING * LOG2E : 1.0f;
    __half* outbase = (bx < NHEADS) ? (q16 + ((long)bx * T + m0) * HDIM)
                                    : (k16 + ((long)(bx - NHEADS) * T + m0) * HDIM);
#pragma unroll
    for (int it = 0; it < 32; it++) {
        int idx = tid + it * 256;          // 0..8191 half2 slots
        int rl = idx >> 6, c2 = idx & 63;
        int d0 = 2 * c2;
        long trow = m0 + rl;
        float x0 = sx[rl * 130 + d0], x1 = sx[rl * 130 + d0 + 1];
        float o0, o1;
        if (d0 < 64) {
            float y0 = sx[rl * 130 + d0 + 64], y1 = sx[rl * 130 + d0 + 65];
            float c0 = gcos[trow * 64 + d0], c1 = gcos[trow * 64 + d0 + 1];
            float s0 = gsin[trow * 64 + d0], s1 = gsin[trow * 64 + d0 + 1];
            o0 = x0 * c0 - y0 * s0;
            o1 = x1 * c1 - y1 * s1;
        } else {
            int dd = d0 - 64;
            float y0 = sx[rl * 130 + dd], y1 = sx[rl * 130 + dd + 1];
            float c0 = gcos[trow * 64 + dd], c1 = gcos[trow * 64 + dd + 1];
            float s0 = gsin[trow * 64 + dd], s1 = gsin[trow * 64 + dd + 1];
            o0 = x0 * c0 + y0 * s0;
            o1 = x1 * c1 + y1 * s1;
        }
        *(__half2*)&outbase[(long)rl * HDIM + d0] =
            __floats2half2_rn(o0 * oscale, o1 * oscale);
    }
}

// =====================================================================
// plain GEMM (fp32 out) for WO
// =====================================================================
__global__ __launch_bounds__(256, 2) void gemm_h16f(
    const __half* __restrict__ A, const __half* __restrict__ B,
    float* __restrict__ C, int M, int N, int K)
{
    extern __shared__ __half smh[];

    int tid = threadIdx.x;
    int lane = tid & 31, warp = tid >> 5;
    int gid = lane >> 2, tig = lane & 3;
    int wm = warp >> 2, wn = warp & 3;
    int m0 = blockIdx.y * 128, n0 = blockIdx.x * 128;

    float acc[4][4][4];
    GEMM_MAINLOOP(A, B, K)

#pragma unroll
    for (int mt = 0; mt < 4; mt++) {
        int row = m0 + wm * 64 + mt * 16 + gid;
#pragma unroll
        for (int nt = 0; nt < 4; nt++) {
            int col = n0 + wn * 32 + nt * 8 + 2 * tig;
            *(float2*)&C[(long)row * N + col] = make_float2(acc[mt][nt][0], acc[mt][nt][1]);
            *(float2*)&C[(long)(row + 8) * N + col] = make_float2(acc[mt][nt][2], acc[mt][nt][3]);
        }
    }
}

// =====================================================================
// fp16 flash attention (causal, GQA). Output fp16.
// Balanced 296-CTA schedule (2/SM), antipodal two-tile pairing,
// diagonal warp-skip, ex2.approx.f16x2 softmax, predicated rescale.
// V now head-major (stride HDIM).
// =====================================================================
#define FSTR 136
#define FQ_H (128 * FSTR)
#define FKV_H (64 * FSTR)
#define FLASH_SMEM ((FQ_H + 4 * FKV_H) * 2)   // 104448 B

__global__ __launch_bounds__(256, 2) void flash_h16(
    const __half* __restrict__ Q, const __half* __restrict__ Kh,
    const __half* __restrict__ Vh, __half* __restrict__ O)
{
    extern __shared__ __half smf[];
    __half* Qs = smf;                 // [128][136]
    __half* Ks = smf + FQ_H;          // [2][64][136]
    __half* Vs = Ks + 2 * FKV_H;      // [2][64][136]

    int cta = blockIdx.x;             // 0..295
    int tid = threadIdx.x;
    int lane = tid & 31, warp = tid >> 5;
    int gid = lane >> 2, tig = lane & 3;

    for (int ti = 0; ti < 2; ti++) {
        int t;
        if (ti == 0) {
            t = cta;                          // tiles 0..295 (big half)
        } else {
            if (cta < 80) break;              // no second tile
            t = (NTILES - 1) - (cta - 80);    // cta=80 -> 511, cta=295 -> 296
        }
        int qb = (NQB - 1) - (t >> 5);        // descending work order
        int h  = t & 31;
        int kvh = h >> 2;
        int q0 = qb * 128;

        const __half* Qg = Q + ((long)h * T + q0) * HDIM;
        const __half* Kg = Kh + (long)kvh * T * HDIM;
        const __half* Vg = Vh + (long)kvh * T * HDIM;

        __syncthreads();   // smem from previous tile fully consumed

        // prologue: Q tile + KV block 0
#pragma unroll
        for (int i = 0; i < 8; i++) {
            int idx = tid + i * 256;
            int r = idx >> 4, c = idx & 15;
            cp16(smem_u32(Qs + r * FSTR + c * 8), Qg + r * HDIM + c * 8);
        }
#pragma unroll
        for (int i = 0; i < 4; i++) {
            int idx = tid + i * 256;
            int r = idx >> 4, c = idx & 15;
            cp16(smem_u32(Ks + r * FSTR + c * 8), Kg + (long)r * HDIM + c * 8);
            cp16(smem_u32(Vs + r * FSTR + c * 8), Vg + (long)r * HDIM + c * 8);
        }
        cp_commit();

        float m0s = -1e30f, m1s = -1e30f, l0s = 0.f, l1s = 0.f;
        float oacc[16][4];
#pragma unroll
        for (int nt = 0; nt < 16; nt++)
#pragma unroll
            for (int r = 0; r < 4; r++) oacc[nt][r] = 0.f;

        int r0 = q0 + warp * 16 + gid;
        int r1 = r0 + 8;
        int kbmax = 2 * qb + 1;

        for (int kb = 0; kb <= kbmax; kb++) {
            cp_wait<0>();
            __syncthreads();

            if (kb < kbmax) {
                __half* Kn = Ks + ((kb + 1) & 1) * FKV_H;
                __half* Vn = Vs + ((kb + 1) & 1) * FKV_H;
                long rowoff = (long)(kb + 1) * 64;
#pragma unroll
                for (int i = 0; i < 4; i++) {
                    int idx = tid + i * 256;
                    int r = idx >> 4, c = idx & 15;
                    cp16(smem_u32(Kn + r * FSTR + c * 8), Kg + (rowoff + r) * HDIM + c * 8);
                    cp16(smem_u32(Vn + r * FSTR + c * 8), Vg + (rowoff + r) * HDIM + c * 8);
                }
            }
            cp_commit();

            // diagonal half-block: warps 0-3 fully masked -> exact skip
            if (kb == kbmax && warp < 4) continue;

            const __half* Kc = Ks + (kb & 1) * FKV_H;
            const __half* Vc = Vs + (kb & 1) * FKV_H;

            // ---- S = Q K^T ----
            float sacc[8][4];
#pragma unroll
            for (int nt = 0; nt < 8; nt++)
#pragma unroll
                for (int r = 0; r < 4; r++) sacc[nt][r] = 0.f;

#pragma unroll
            for (int kc = 0; kc < 8; kc++) {
                unsigned aq[4];
                {
                    int row = warp * 16 + (lane & 15);
                    int c2  = kc * 2 + (lane >> 4);
                    ldsm4(aq, smem_u32(Qs + row * FSTR + c2 * 8));
                }
#pragma unroll
                for (int ntp = 0; ntp < 4; ntp++) {
                    unsigned bk[4];
                    int row = ntp * 16 + (lane & 7) + ((lane >> 4) << 3);
                    int c2  = kc * 2 + ((lane >> 3) & 1);
                    ldsm4(bk, smem_u32(Kc + row * FSTR + c2 * 8));
                    mma_f16(sacc[2*ntp],   aq, bk[0], bk[1]);
                    mma_f16(sacc[2*ntp+1], aq, bk[2], bk[3]);
                }
            }

            // ---- causal mask (last two kv blocks only) ----
            if (kb >= 2 * qb) {
#pragma unroll
                for (int nt = 0; nt < 8; nt++) {
                    int colb = kb * 64 + nt * 8 + 2 * tig;
                    if (colb > r0)     sacc[nt][0] = -1e30f;
                    if (colb + 1 > r0) sacc[nt][1] = -1e30f;
                    if (colb > r1)     sacc[nt][2] = -1e30f;
                    if (colb + 1 > r1) sacc[nt][3] = -1e30f;
                }
            }

            // ---- online softmax (fp16x2 exps, predicated rescale) ----
            float mx0 = -1e30f, mx1 = -1e30f;
#pragma unroll
            for (int nt = 0; nt < 8; nt++) {
                mx0 = fmaxf(mx0, fmaxf(sacc[nt][0], sacc[nt][1]));
                mx1 = fmaxf(mx1, fmaxf(sacc[nt][2], sacc[nt][3]));
            }
            mx0 = fmaxf(mx0, __shfl_xor_sync(0xffffffffu, mx0, 1));
            mx0 = fmaxf(mx0, __shfl_xor_sync(0xffffffffu, mx0, 2));
            mx1 = fmaxf(mx1, __shfl_xor_sync(0xffffffffu, mx1, 1));
            mx1 = fmaxf(mx1, __shfl_xor_sync(0xffffffffu, mx1, 2));

            float mn0 = fmaxf(m0s, mx0);
            float mn1 = fmaxf(m1s, mx1);
            bool rescale = (mn0 > m0s) || (mn1 > m1s);

            unsigned pexp[8][2];
            float ls0 = 0.f, ls1 = 0.f;
#pragma unroll
            for (int nt = 0; nt < 8; nt++) {
                unsigned e01 = h2exp2(pack_h2(sacc[nt][0] - mn0, sacc[nt][1] - mn0));
                unsigned e23 = h2exp2(pack_h2(sacc[nt][2] - mn1, sacc[nt][3] - mn1));
                pexp[nt][0] = e01;
                pexp[nt][1] = e23;
                float2 f01 = __half22float2(*reinterpret_cast<__half2*>(&e01));
                float2 f23 = __half22float2(*reinterpret_cast<__half2*>(&e23));
                ls0 += f01.x + f01.y;
                ls1 += f23.x + f23.y;
            }
            ls0 += __shfl_xor_sync(0xffffffffu, ls0, 1);
            ls0 += __shfl_xor_sync(0xffffffffu, ls0, 2);
            ls1 += __shfl_xor_sync(0xffffffffu, ls1, 1);
            ls1 += __shfl_xor_sync(0xffffffffu, ls1, 2);

            if (rescale) {
                float corr0 = exp2f(m0s - mn0);
                float corr1 = exp2f(m1s - mn1);
                l0s = l0s * corr0 + ls0;
                l1s = l1s * corr1 + ls1;
#pragma unroll
                for (int nt = 0; nt < 16; nt++) {
                    oacc[nt][0] *= corr0;
                    oacc[nt][1] *= corr0;
                    oacc[nt][2] *= corr1;
                    oacc[nt][3] *= corr1;
                }
                m0s = mn0;
                m1s = mn1;
            } else {
                l0s += ls0;
                l1s += ls1;
            }

            // ---- O += P V (P fragments come straight from h2exp2) ----
#pragma unroll
            for (int kc2 = 0; kc2 < 4; kc2++) {
                unsigned ap[4];
                ap[0] = pexp[2*kc2][0];
                ap[1] = pexp[2*kc2][1];
                ap[2] = pexp[2*kc2+1][0];
                ap[3] = pexp[2*kc2+1][1];
#pragma unroll
                for (int ntp = 0; ntp < 8; ntp++) {
                    unsigned bv[4];
                    int row = kc2 * 16 + (lane & 7) + (((lane >> 3) & 1) << 3);
                    int c2  = ntp * 2 + (lane >> 4);
                    ldsm4t(bv, smem_u32(Vc + row * FSTR + c2 * 8));
                    mma_f16(oacc[2*ntp],   ap, bv[0], bv[1]);
                    mma_f16(oacc[2*ntp+1], ap, bv[2], bv[3]);
                }
            }
        }

        float inv0 = 1.0f / l0s;
        float inv1 = 1.0f / l1s;
#pragma unroll
        for (int nt = 0; nt < 16; nt++) {
            int col = h * HDIM + nt * 8 + 2 * tig;
            *(__half2*)&O[(long)r0 * QSIZE + col] =
                __floats2half2_rn(oacc[nt][0] * inv0, oacc[nt][1] * inv0);
            *(__half2*)&O[(long)r1 * QSIZE + col] =
                __floats2half2_rn(oacc[nt][2] * inv1, oacc[nt][3] * inv1);
        }
    }
}

// =====================================================================
// launch
// =====================================================================
extern "C" void kernel_launch(void* const* d_in, const int* in_sizes, int n_in,
                              void* d_out, int out_size)
{
    const int*   positions = (const int*)d_in[0];
    const float* hidden    = (const float*)d_in[1];
    const float* wqkv      = (const float*)d_in[2];
    const float* wo        = (const float*)d_in[3];
    const float* qnw       = (const float*)d_in[4];
    const float* knw       = (const float*)d_in[5];
    float* out = (float*)d_out;

    __half *h16, *wqkv16, *wo16, *q16, *k16, *v16, *o16;
    float *gcos, *gsin;
    cudaGetSymbolAddress((void**)&h16, g_h16);
    cudaGetSymbolAddress((void**)&wqkv16, g_wqkv16);
    cudaGetSymbolAddress((void**)&wo16, g_wo16);
    cudaGetSymbolAddress((void**)&q16, g_q16);
    cudaGetSymbolAddress((void**)&k16, g_k16);
    cudaGetSymbolAddress((void**)&v16, g_v16);
    cudaGetSymbolAddress((void**)&o16, g_o16);
    cudaGetSymbolAddress((void**)&gcos, g_cos);
    cudaGetSymbolAddress((void**)&gsin, g_sin);

    static bool attr_done = false;
    if (!attr_done) {
        cudaFuncSetAttribute(gemm_qkv_fused,
                             cudaFuncAttributeMaxDynamicSharedMemorySize, GEMM_SMEM);
        cudaFuncSetAttribute(gemm_h16f,
                             cudaFuncAttributeMaxDynamicSharedMemorySize, GEMM_SMEM);
        cudaFuncSetAttribute(flash_h16,
                             cudaFuncAttributeMaxDynamicSharedMemorySize, FLASH_SMEM);
        attr_done = true;
    }

    // 0) converts + rope tables
    f2h_all_kernel<<<4096, 256>>>(hidden, wqkv, wo, h16, wqkv16, wo16);
    rope_table_kernel<<<(T * 64) / 256, 256>>>(positions, gcos, gsin);

    // 1) fused QKV GEMM + RMSNorm + RoPE -> q16/k16/v16 head-major
    {
        dim3 grid(QKVW / 128, T / 128);
        gemm_qkv_fused<<<grid, 256, GEMM_SMEM>>>(h16, wqkv16, q16, k16, v16,
                                                 gcos, gsin, qnw, knw);
    }
    // 2) causal flash attention -> o16, balanced 296-CTA schedule
    {
        flash_h16<<<FGRID, 256, FLASH_SMEM>>>(q16, k16, v16, o16);
    }
    // 3) out = o @ wo^T   [2048, 2048] fp32
    {
        dim3 grid(HIDDEN / 128, T / 128);
        gemm_h16f<<<grid, 256, GEMM_SMEM>>>(o16, wo16, out, T, HIDDEN, QSIZE);
    }
}

// round 16
// speedup vs baseline: 1.5668x; 1.0148x over previous
#include <cuda_runtime.h>
#include <cuda_fp16.h>
#include <math.h>

// ---------------- constants ----------------
#define T        2048
#define HIDDEN   2048
#define NHEADS   32
#define NKV      8
#define HDIM     128
#define QSIZE    (NHEADS * HDIM)          // 4096
#define KVSIZE   (NKV * HDIM)             // 1024
#define QKVW     (QSIZE + 2 * KVSIZE)     // 6144
#define SCALING  0.08838834764831845f     // 1/sqrt(128)
#define LOG2E    1.4426950408889634f
#define L2_10000_D64 0.20762050593046f    // log2(10000)/64

#define NQB      (T / 128)                // 16 q-tiles per head
#define NTILES   (NQB * NHEADS)           // 512
#define FGRID    296                      // 2 CTAs x 148 SMs

// ---------------- scratch (no allocations allowed) ----------------
__device__ __half g_h16[T * HIDDEN];           // hidden fp16
__device__ __half g_wqkv16[QKVW * HIDDEN];     // wqkv fp16
__device__ __half g_wo16[HIDDEN * QSIZE];      // wo fp16
__device__ __half g_q16[NHEADS * T * HDIM];    // head-major, scaled by 1/sqrt(D)*log2e
__device__ __half g_k16[NKV * T * HDIM];       // head-major
__device__ __half g_v16[NKV * T * HDIM];       // head-major
__device__ __half g_o16[T * QSIZE];            // attention out fp16
__device__ float  g_cos[T * 64];               // rope tables
__device__ float  g_sin[T * 64];

// ---------------- ptx helpers ----------------
__device__ __forceinline__ unsigned smem_u32(const void* p) {
    return (unsigned)__cvta_generic_to_shared(p);
}
__device__ __forceinline__ void ldsm4(unsigned r[4], unsigned addr) {
    asm volatile("ldmatrix.sync.aligned.m8n8.x4.shared.b16 {%0,%1,%2,%3},[%4];"
                 : "=r"(r[0]), "=r"(r[1]), "=r"(r[2]), "=r"(r[3]) : "r"(addr));
}
__device__ __forceinline__ void ldsm4t(unsigned r[4], unsigned addr) {
    asm volatile("ldmatrix.sync.aligned.m8n8.x4.trans.shared.b16 {%0,%1,%2,%3},[%4];"
                 : "=r"(r[0]), "=r"(r[1]), "=r"(r[2]), "=r"(r[3]) : "r"(addr));
}
__device__ __forceinline__ void mma_f16(float c[4], const unsigned a[4],
                                        unsigned b0, unsigned b1) {
    asm volatile("mma.sync.aligned.m16n8k16.row.col.f32.f16.f16.f32 "
                 "{%0,%1,%2,%3},{%4,%5,%6,%7},{%8,%9},{%0,%1,%2,%3};"
                 : "+f"(c[0]), "+f"(c[1]), "+f"(c[2]), "+f"(c[3])
                 : "r"(a[0]), "r"(a[1]), "r"(a[2]), "r"(a[3]), "r"(b0), "r"(b1));
}
__device__ __forceinline__ void cp16(unsigned saddr, const void* g) {
    asm volatile("cp.async.cg.shared.global [%0],[%1],16;" :: "r"(saddr), "l"(g));
}
__device__ __forceinline__ void cp_commit() {
    asm volatile("cp.async.commit_group;");
}
template <int N>
__device__ __forceinline__ void cp_wait() {
    asm volatile("cp.async.wait_group %0;" :: "n"(N));
}
__device__ __forceinline__ unsigned pack_h2(float a, float b) {
    __half2 h = __floats2half2_rn(a, b);
    return *reinterpret_cast<unsigned*>(&h);
}
// two exps in one MUFU op; result is the packed fp16 pair for the PV MMA
__device__ __forceinline__ unsigned h2exp2(unsigned x) {
    unsigned r;
    asm("ex2.approx.f16x2 %0, %1;" : "=r"(r) : "r"(x));
    return r;
}

// =====================================================================
// fused fp32->fp16 convert (hidden+wqkv+wo) + rope table, one launch
// =====================================================================
#define N_H   ((long)T * HIDDEN)
#define N_WQ  ((long)QKVW * HIDDEN)
#define N_WO  ((long)HIDDEN * QSIZE)
#define N_ALL (N_H + N_WQ + N_WO)

__global__ void prep_kernel(const float* __restrict__ hid,
                            const float* __restrict__ wqkv,
                            const float* __restrict__ wo,
                            __half* __restrict__ h16,
                            __half* __restrict__ wqkv16,
                            __half* __restrict__ wo16,
                            const int* __restrict__ positions,
                            float* __restrict__ gcos,
                            float* __restrict__ gsin)
{
    long i = ((long)blockIdx.x * blockDim.x + threadIdx.x) * 4;
    long stride = (long)gridDim.x * blockDim.x * 4;
    for (; i < N_ALL; i += stride) {
        const float* src;
        __half* dst;
        long off;
        if (i < N_H)            { src = hid;  dst = h16;    off = i; }
        else if (i < N_H + N_WQ){ src = wqkv; dst = wqkv16; off = i - N_H; }
        else                    { src = wo;   dst = wo16;   off = i - N_H - N_WQ; }
        float4 v = *(const float4*)(src + off);
        *(__half2*)(dst + off)     = __floats2half2_rn(v.x, v.y);
        *(__half2*)(dst + off + 2) = __floats2half2_rn(v.z, v.w);
    }
    // rope table tail: T*64 entries
    int gtid = blockIdx.x * blockDim.x + threadIdx.x;
    int gthreads = gridDim.x * blockDim.x;
    for (int j = gtid; j < T * 64; j += gthreads) {
        int t = j >> 6, d = j & 63;
        float ang = (float)positions[t] * exp2f(-(float)d * L2_10000_D64);
        float c, s;
        sincosf(ang, &s, &c);
        gcos[j] = c;
        gsin[j] = s;
    }
}

// =====================================================================
// GEMM mainloop config (measured-best): 128x128 block, BK=64,
// 3-stage cp.async pipeline, 256 threads, 2 CTAs/SM.
// =====================================================================
#define GSTRH 72
#define STAGE_H (256 * GSTRH)
#define GS 3
#define GEMM_SMEM (GS * STAGE_H * 2)      // 110592 B

#define GEMM_MAINLOOP(A, B, K)                                               \
    int ch   = tid & 7;                                                      \
    int row0 = tid >> 3;                                                     \
    const __half* gsrc[8];                                                   \
    _Pragma("unroll")                                                        \
    for (int i = 0; i < 8; i++) {                                            \
        int row = row0 + 32 * i;                                             \
        gsrc[i] = (row < 128 ? (A) + (long)(m0 + row) * (K)                  \
                             : (B) + (long)(n0 + row - 128) * (K)) + ch * 8; \
    }                                                                        \
    unsigned sdst[8];                                                        \
    _Pragma("unroll")                                                        \
    for (int i = 0; i < 8; i++)                                              \
        sdst[i] = smem_u32(smh + (row0 + 32 * i) * GSTRH + ch * 8);          \
    _Pragma("unroll")                                                        \
    for (int mt = 0; mt < 4; mt++)                                           \
        _Pragma("unroll")                                                    \
        for (int nt = 0; nt < 4; nt++)                                       \
            _Pragma("unroll")                                                \
            for (int r = 0; r < 4; r++) acc[mt][nt][r] = 0.f;                \
    int nk = (K) >> 6;                                                       \
    _Pragma("unroll")                                                        \
    for (int s = 0; s < 2; s++) {                                            \
        _Pragma("unroll")                                                    \
        for (int i = 0; i < 8; i++)                                          \
            cp16(sdst[i] + s * (STAGE_H * 2), gsrc[i] + (long)s * 64);       \
        cp_commit();                                                         \
    }                                                                        \
    for (int k = 0; k < nk; k++) {                                           \
        cp_wait<1>();                                                        \
        __syncthreads();                                                     \
        if (k + 2 < nk) {                                                    \
            int sb = ((k + 2) % GS) * (STAGE_H * 2);                         \
            long kof = (long)(k + 2) * 64;                                   \
            _Pragma("unroll")                                                \
            for (int i = 0; i < 8; i++)                                      \
                cp16(sdst[i] + sb, gsrc[i] + kof);                           \
        }                                                                    \
        cp_commit();                                                         \
        const __half* Ac = smh + (k % GS) * STAGE_H;                         \
        const __half* Bc = Ac + 128 * GSTRH;                                 \
        _Pragma("unroll")                                                    \
        for (int kc = 0; kc < 4; kc++) {                                     \
            unsigned aq[4][4], bk[2][4];                                     \
            _Pragma("unroll")                                                \
            for (int mt = 0; mt < 4; mt++) {                                 \
                int row = wm * 64 + mt * 16 + (lane & 15);                   \
                int c2  = kc * 2 + (lane >> 4);                              \
                ldsm4(aq[mt], smem_u32(Ac + row * GSTRH + c2 * 8));          \
            }                                                                \
            _Pragma("unroll")                                                \
            for (int ntp = 0; ntp < 2; ntp++) {                              \
                int row = wn * 32 + ntp * 16 + (lane & 7) + ((lane >> 4) << 3); \
                int c2  = kc * 2 + ((lane >> 3) & 1);                        \
                ldsm4(bk[ntp], smem_u32(Bc + row * GSTRH + c2 * 8));         \
            }                                                                \
            _Pragma("unroll")                                                \
            for (int mt = 0; mt < 4; mt++)                                   \
                _Pragma("unroll")                                            \
                for (int ntp = 0; ntp < 2; ntp++) {                          \
                    mma_f16(acc[mt][2*ntp],   aq[mt], bk[ntp][0], bk[ntp][1]); \
                    mma_f16(acc[mt][2*ntp+1], aq[mt], bk[ntp][2], bk[ntp][3]); \
                }                                                            \
        }                                                                    \
    }

// =====================================================================
// QKV GEMM with FUSED RMSNorm + RoPE + head-major fp16 repack.
// =====================================================================
__global__ __launch_bounds__(256, 2) void gemm_qkv_fused(
    const __half* __restrict__ A, const __half* __restrict__ B,
    __half* __restrict__ q16, __half* __restrict__ k16, __half* __restrict__ v16,
    const float* __restrict__ gcos, const float* __restrict__ gsin,
    const float* __restrict__ qw, const float* __restrict__ kw)
{
    extern __shared__ __half smh[];

    int tid = threadIdx.x;
    int lane = tid & 31, warp = tid >> 5;
    int gid = lane >> 2, tig = lane & 3;
    int wm = warp >> 2, wn = warp & 3;
    int m0 = blockIdx.y * 128, n0 = blockIdx.x * 128;
    int bx = blockIdx.x;

    float acc[4][4][4];
    GEMM_MAINLOOP(A, B, HIDDEN)

    __syncthreads();   // mainloop smem fully consumed by all warps

    if (bx >= NHEADS + NKV) {
        __half* vout = v16 + ((long)(bx - NHEADS - NKV) * T + m0) * HDIM;
#pragma unroll
        for (int mt = 0; mt < 4; mt++) {
            int rl = wm * 64 + mt * 16 + gid;
#pragma unroll
            for (int nt = 0; nt < 4; nt++) {
                int col = wn * 32 + nt * 8 + 2 * tig;
                *(__half2*)&vout[(long)rl * HDIM + col] =
                    __floats2half2_rn(acc[mt][nt][0], acc[mt][nt][1]);
                *(__half2*)&vout[(long)(rl + 8) * HDIM + col] =
                    __floats2half2_rn(acc[mt][nt][2], acc[mt][nt][3]);
            }
        }
        return;
    }

    float* sx    = (float*)smh;            // [128][130]
    float* part  = sx + 128 * 130;         // [128][4]
    float* norml = part + 128 * 4;         // [128]

    float ssq0[4], ssq1[4];
#pragma unroll
    for (int mt = 0; mt < 4; mt++) {
        float a0 = 0.f, a1 = 0.f;
#pragma unroll
        for (int nt = 0; nt < 4; nt++) {
            a0 += acc[mt][nt][0] * acc[mt][nt][0] + acc[mt][nt][1] * acc[mt][nt][1];
            a1 += acc[mt][nt][2] * acc[mt][nt][2] + acc[mt][nt][3] * acc[mt][nt][3];
        }
        a0 += __shfl_xor_sync(0xffffffffu, a0, 1);
        a0 += __shfl_xor_sync(0xffffffffu, a0, 2);
        a1 += __shfl_xor_sync(0xffffffffu, a1, 1);
        a1 += __shfl_xor_sync(0xffffffffu, a1, 2);
        ssq0[mt] = a0;
        ssq1[mt] = a1;
    }
    if (tig == 0) {
#pragma unroll
        for (int mt = 0; mt < 4; mt++) {
            int rl = wm * 64 + mt * 16 + gid;
            part[rl * 4 + wn] = ssq0[mt];
            part[(rl + 8) * 4 + wn] = ssq1[mt];
        }
    }
    __syncthreads();

    if (tid < 128) {
        float tot = part[tid * 4] + part[tid * 4 + 1] + part[tid * 4 + 2] + part[tid * 4 + 3];
        norml[tid] = rsqrtf(tot * (1.0f / (float)HDIM) + 1e-6f);
    }
    __syncthreads();

    const float* w = (bx < NHEADS) ? qw : kw;
#pragma unroll
    for (int mt = 0; mt < 4; mt++) {
        int rl = wm * 64 + mt * 16 + gid;
        float nv0 = norml[rl], nv1 = norml[rl + 8];
#pragma unroll
        for (int nt = 0; nt < 4; nt++) {
            int col = wn * 32 + nt * 8 + 2 * tig;
            float w0 = w[col], w1 = w[col + 1];
            sx[rl * 130 + col]           = acc[mt][nt][0] * nv0 * w0;
            sx[rl * 130 + col + 1]       = acc[mt][nt][1] * nv0 * w1;
            sx[(rl + 8) * 130 + col]     = acc[mt][nt][2] * nv1 * w0;
            sx[(rl + 8) * 130 + col + 1] = acc[mt][nt][3] * nv1 * w1;
        }
    }
    __syncthreads();

    float oscale = (bx < NHEADS) ? SCALING * LOG2E : 1.0f;
    __half* outbase = (bx < NHEADS) ? (q16 + ((long)bx * T + m0) * HDIM)
                                    : (k16 + ((long)(bx - NHEADS) * T + m0) * HDIM);
#pragma unroll
    for (int it = 0; it < 32; it++) {
        int idx = tid + it * 256;
        int rl = idx >> 6, c2 = idx & 63;
        int d0 = 2 * c2;
        long trow = m0 + rl;
        float x0 = sx[rl * 130 + d0], x1 = sx[rl * 130 + d0 + 1];
        float o0, o1;
        if (d0 < 64) {
            float y0 = sx[rl * 130 + d0 + 64], y1 = sx[rl * 130 + d0 + 65];
            float c0 = gcos[trow * 64 + d0], c1 = gcos[trow * 64 + d0 + 1];
            float s0 = gsin[trow * 64 + d0], s1 = gsin[trow * 64 + d0 + 1];
            o0 = x0 * c0 - y0 * s0;
            o1 = x1 * c1 - y1 * s1;
        } else {
            int dd = d0 - 64;
            float y0 = sx[rl * 130 + dd], y1 = sx[rl * 130 + dd + 1];
            float c0 = gcos[trow * 64 + dd], c1 = gcos[trow * 64 + dd + 1];
            float s0 = gsin[trow * 64 + dd], s1 = gsin[trow * 64 + dd + 1];
            o0 = x0 * c0 + y0 * s0;
            o1 = x1 * c1 + y1 * s1;
        }
        *(__half2*)&outbase[(long)rl * HDIM + d0] =
            __floats2half2_rn(o0 * oscale, o1 * oscale);
    }
}

// =====================================================================
// plain GEMM (fp32 out) for WO
// =====================================================================
__global__ __launch_bounds__(256, 2) void gemm_h16f(
    const __half* __restrict__ A, const __half* __restrict__ B,
    float* __restrict__ C, int M, int N, int K)
{
    extern __shared__ __half smh[];

    int tid = threadIdx.x;
    int lane = tid & 31, warp = tid >> 5;
    int gid = lane >> 2, tig = lane & 3;
    int wm = warp >> 2, wn = warp & 3;
    int m0 = blockIdx.y * 128, n0 = blockIdx.x * 128;

    float acc[4][4][4];
    GEMM_MAINLOOP(A, B, K)

#pragma unroll
    for (int mt = 0; mt < 4; mt++) {
        int row = m0 + wm * 64 + mt * 16 + gid;
#pragma unroll
        for (int nt = 0; nt < 4; nt++) {
            int col = n0 + wn * 32 + nt * 8 + 2 * tig;
            *(float2*)&C[(long)row * N + col] = make_float2(acc[mt][nt][0], acc[mt][nt][1]);
            *(float2*)&C[(long)(row + 8) * N + col] = make_float2(acc[mt][nt][2], acc[mt][nt][3]);
        }
    }
}

// =====================================================================
// fp16 flash attention (causal, GQA). Output fp16.
// Balanced 296-CTA schedule, antipodal pairing, diagonal warp-skip.
// SPLIT K/V commit groups: QK waits only on K (wait<1>); V retires
// after softmax (wait<1>), gaining the QK+softmax window.
// =====================================================================
#define FSTR 136
#define FQ_H (128 * FSTR)
#define FKV_H (64 * FSTR)
#define FLASH_SMEM ((FQ_H + 4 * FKV_H) * 2)   // 104448 B

__global__ __launch_bounds__(256, 2) void flash_h16(
    const __half* __restrict__ Q, const __half* __restrict__ Kh,
    const __half* __restrict__ Vh, __half* __restrict__ O)
{
    extern __shared__ __half smf[];
    __half* Qs = smf;                 // [128][136]
    __half* Ks = smf + FQ_H;          // [2][64][136]
    __half* Vs = Ks + 2 * FKV_H;      // [2][64][136]

    int cta = blockIdx.x;             // 0..295
    int tid = threadIdx.x;
    int lane = tid & 31, warp = tid >> 5;
    int gid = lane >> 2, tig = lane & 3;

    for (int ti = 0; ti < 2; ti++) {
        int t;
        if (ti == 0) {
            t = cta;
        } else {
            if (cta < 80) break;
            t = (NTILES - 1) - (cta - 80);
        }
        int qb = (NQB - 1) - (t >> 5);
        int h  = t & 31;
        int kvh = h >> 2;
        int q0 = qb * 128;

        const __half* Qg = Q + ((long)h * T + q0) * HDIM;
        const __half* Kg = Kh + (long)kvh * T * HDIM;
        const __half* Vg = Vh + (long)kvh * T * HDIM;

        __syncthreads();   // smem from previous tile fully consumed

        // prologue: [Q + K0] group, then [V0] group
#pragma unroll
        for (int i = 0; i < 8; i++) {
            int idx = tid + i * 256;
            int r = idx >> 4, c = idx & 15;
            cp16(smem_u32(Qs + r * FSTR + c * 8), Qg + r * HDIM + c * 8);
        }
#pragma unroll
        for (int i = 0; i < 4; i++) {
            int idx = tid + i * 256;
            int r = idx >> 4, c = idx & 15;
            cp16(smem_u32(Ks + r * FSTR + c * 8), Kg + (long)r * HDIM + c * 8);
        }
        cp_commit();
#pragma unroll
        for (int i = 0; i < 4; i++) {
            int idx = tid + i * 256;
            int r = idx >> 4, c = idx & 15;
            cp16(smem_u32(Vs + r * FSTR + c * 8), Vg + (long)r * HDIM + c * 8);
        }
        cp_commit();

        float m0s = -1e30f, m1s = -1e30f, l0s = 0.f, l1s = 0.f;
        float oacc[16][4];
#pragma unroll
        for (int nt = 0; nt < 16; nt++)
#pragma unroll
            for (int r = 0; r < 4; r++) oacc[nt][r] = 0.f;

        int r0 = q0 + warp * 16 + gid;
        int r1 = r0 + 8;
        int kbmax = 2 * qb + 1;

        for (int kb = 0; kb <= kbmax; kb++) {
            cp_wait<1>();          // Q+K of current block resolved
            __syncthreads();

            // prefetch K_{kb+1}
            if (kb < kbmax) {
                __half* Kn = Ks + ((kb + 1) & 1) * FKV_H;
                long rowoff = (long)(kb + 1) * 64;
#pragma unroll
                for (int i = 0; i < 4; i++) {
                    int idx = tid + i * 256;
                    int r = idx >> 4, c = idx & 15;
                    cp16(smem_u32(Kn + r * FSTR + c * 8), Kg + (rowoff + r) * HDIM + c * 8);
                }
            }
            cp_commit();

            // diagonal half-block: warps 0-3 fully masked -> exact skip
            if (kb == kbmax && warp < 4) continue;

            const __half* Kc = Ks + (kb & 1) * FKV_H;
            const __half* Vc = Vs + (kb & 1) * FKV_H;

            // ---- S = Q K^T ----
            float sacc[8][4];
#pragma unroll
            for (int nt = 0; nt < 8; nt++)
#pragma unroll
                for (int r = 0; r < 4; r++) sacc[nt][r] = 0.f;

#pragma unroll
            for (int kc = 0; kc < 8; kc++) {
                unsigned aq[4];
                {
                    int row = warp * 16 + (lane & 15);
                    int c2  = kc * 2 + (lane >> 4);
                    ldsm4(aq, smem_u32(Qs + row * FSTR + c2 * 8));
                }
#pragma unroll
                for (int ntp = 0; ntp < 4; ntp++) {
                    unsigned bk[4];
                    int row = ntp * 16 + (lane & 7) + ((lane >> 4) << 3);
                    int c2  = kc * 2 + ((lane >> 3) & 1);
                    ldsm4(bk, smem_u32(Kc + row * FSTR + c2 * 8));
                    mma_f16(sacc[2*ntp],   aq, bk[0], bk[1]);
                    mma_f16(sacc[2*ntp+1], aq, bk[2], bk[3]);
                }
            }

            // ---- causal mask (last two kv blocks only) ----
            if (kb >= 2 * qb) {
#pragma unroll
                for (int nt = 0; nt < 8; nt++) {
                    int colb = kb * 64 + nt * 8 + 2 * tig;
                    if (colb > r0)     sacc[nt][0] = -1e30f;
                    if (colb + 1 > r0) sacc[nt][1] = -1e30f;
                    if (colb > r1)     sacc[nt][2] = -1e30f;
                    if (colb + 1 > r1) sacc[nt][3] = -1e30f;
                }
            }

            // ---- online softmax (fp16x2 exps, predicated rescale) ----
            float mx0 = -1e30f, mx1 = -1e30f;
#pragma unroll
            for (int nt = 0; nt < 8; nt++) {
                mx0 = fmaxf(mx0, fmaxf(sacc[nt][0], sacc[nt][1]));
                mx1 = fmaxf(mx1, fmaxf(sacc[nt][2], sacc[nt][3]));
            }
            mx0 = fmaxf(mx0, __shfl_xor_sync(0xffffffffu, mx0, 1));
            mx0 = fmaxf(mx0, __shfl_xor_sync(0xffffffffu, mx0, 2));
            mx1 = fmaxf(mx1, __shfl_xor_sync(0xffffffffu, mx1, 1));
            mx1 = fmaxf(mx1, __shfl_xor_sync(0xffffffffu, mx1, 2));

            float mn0 = fmaxf(m0s, mx0);
            float mn1 = fmaxf(m1s, mx1);
            bool rescale = (mn0 > m0s) || (mn1 > m1s);

            unsigned pexp[8][2];
            float ls0 = 0.f, ls1 = 0.f;
#pragma unroll
            for (int nt = 0; nt < 8; nt++) {
                unsigned e01 = h2exp2(pack_h2(sacc[nt][0] - mn0, sacc[nt][1] - mn0));
                unsigned e23 = h2exp2(pack_h2(sacc[nt][2] - mn1, sacc[nt][3] - mn1));
                pexp[nt][0] = e01;
                pexp[nt][1] = e23;
                float2 f01 = __half22float2(*reinterpret_cast<__half2*>(&e01));
                float2 f23 = __half22float2(*reinterpret_cast<__half2*>(&e23));
                ls0 += f01.x + f01.y;
                ls1 += f23.x + f23.y;
            }
            ls0 += __shfl_xor_sync(0xffffffffu, ls0, 1);
            ls0 += __shfl_xor_sync(0xffffffffu, ls0, 2);
            ls1 += __shfl_xor_sync(0xffffffffu, ls1, 1);
            ls1 += __shfl_xor_sync(0xffffffffu, ls1, 2);

            if (rescale) {
                float corr0 = exp2f(m0s - mn0);
                float corr1 = exp2f(m1s - mn1);
                l0s = l0s * corr0 + ls0;
                l1s = l1s * corr1 + ls1;
#pragma unroll
                for (int nt = 0; nt < 16; nt++) {
                    oacc[nt][0] *= corr0;
                    oacc[nt][1] *= corr0;
                    oacc[nt][2] *= corr1;
                    oacc[nt][3] *= corr1;
                }
                m0s = mn0;
                m1s = mn1;
            } else {
                l0s += ls0;
                l1s += ls1;
            }

            // ---- V of current block resolved; prefetch V_{kb+1} ----
            cp_wait<1>();
            if (kb < kbmax) {
                __half* Vn = Vs + ((kb + 1) & 1) * FKV_H;
                long rowoff = (long)(kb + 1) * 64;
#pragma unroll
                for (int i = 0; i < 4; i++) {
                    int idx = tid + i * 256;
                    int r = idx >> 4, c = idx & 15;
                    cp16(smem_u32(Vn + r * FSTR + c * 8), Vg + (rowoff + r) * HDIM + c * 8);
                }
            }
            cp_commit();

            // ---- O += P V (P fragments come straight from h2exp2) ----
#pragma unroll
            for (int kc2 = 0; kc2 < 4; kc2++) {
                unsigned ap[4];
                ap[0] = pexp[2*kc2][0];
                ap[1] = pexp[2*kc2][1];
                ap[2] = pexp[2*kc2+1][0];
                ap[3] = pexp[2*kc2+1][1];
#pragma unroll
                for (int ntp = 0; ntp < 8; ntp++) {
                    unsigned bv[4];
                    int row = kc2 * 16 + (lane & 7) + (((lane >> 3) & 1) << 3);
                    int c2  = ntp * 2 + (lane >> 4);
                    ldsm4t(bv, smem_u32(Vc + row * FSTR + c2 * 8));
                    mma_f16(oacc[2*ntp],   ap, bv[0], bv[1]);
                    mma_f16(oacc[2*ntp+1], ap, bv[2], bv[3]);
                }
            }
        }

        float inv0 = 1.0f / l0s;
        float inv1 = 1.0f / l1s;
#pragma unroll
        for (int nt = 0; nt < 16; nt++) {
            int col = h * HDIM + nt * 8 + 2 * tig;
            *(__half2*)&O[(long)r0 * QSIZE + col] =
                __floats2half2_rn(oacc[nt][0] * inv0, oacc[nt][1] * inv0);
            *(__half2*)&O[(long)r1 * QSIZE + col] =
                __floats2half2_rn(oacc[nt][2] * inv1, oacc[nt][3] * inv1);
        }
    }
}

// =====================================================================
// launch
// =====================================================================
extern "C" void kernel_launch(void* const* d_in, const int* in_sizes, int n_in,
                              void* d_out, int out_size)
{
    const int*   positions = (const int*)d_in[0];
    const float* hidden    = (const float*)d_in[1];
    const float* wqkv      = (const float*)d_in[2];
    const float* wo        = (const float*)d_in[3];
    const float* qnw       = (const float*)d_in[4];
    const float* knw       = (const float*)d_in[5];
    float* out = (float*)d_out;

    __half *h16, *wqkv16, *wo16, *q16, *k16, *v16, *o16;
    float *gcos, *gsin;
    cudaGetSymbolAddress((void**)&h16, g_h16);
    cudaGetSymbolAddress((void**)&wqkv16, g_wqkv16);
    cudaGetSymbolAddress((void**)&wo16, g_wo16);
    cudaGetSymbolAddress((void**)&q16, g_q16);
    cudaGetSymbolAddress((void**)&k16, g_k16);
    cudaGetSymbolAddress((void**)&v16, g_v16);
    cudaGetSymbolAddress((void**)&o16, g_o16);
    cudaGetSymbolAddress((void**)&gcos, g_cos);
    cudaGetSymbolAddress((void**)&gsin, g_sin);

    static bool attr_done = false;
    if (!attr_done) {
        cudaFuncSetAttribute(gemm_qkv_fused,
                             cudaFuncAttributeMaxDynamicSharedMemorySize, GEMM_SMEM);
        cudaFuncSetAttribute(gemm_h16f,
                             cudaFuncAttributeMaxDynamicSharedMemorySize, GEMM_SMEM);
        cudaFuncSetAttribute(flash_h16,
                             cudaFuncAttributeMaxDynamicSharedMemorySize, FLASH_SMEM);
        attr_done = true;
    }

    // 0) converts + rope tables (single launch)
    prep_kernel<<<4096, 256>>>(hidden, wqkv, wo, h16, wqkv16, wo16,
                               positions, gcos, gsin);

    // 1) fused QKV GEMM + RMSNorm + RoPE -> q16/k16/v16 head-major
    {
        dim3 grid(QKVW / 128, T / 128);
        gemm_qkv_fused<<<grid, 256, GEMM_SMEM>>>(h16, wqkv16, q16, k16, v16,
                                                 gcos, gsin, qnw, knw);
    }
    // 2) causal flash attention -> o16, balanced 296-CTA schedule
    {
        flash_h16<<<FGRID, 256, FLASH_SMEM>>>(q16, k16, v16, o16);
    }
    // 3) out = o @ wo^T   [2048, 2048] fp32
    {
        dim3 grid(HIDDEN / 128, T / 128);
        gemm_h16f<<<grid, 256, GEMM_SMEM>>>(o16, wo16, out, T, HIDDEN, QSIZE);
    }
}